// round 15
// baseline (speedup 1.0000x reference)
#include <cuda_runtime.h>
#include <cuda_fp16.h>
#include <math.h>
#include <stdint.h>

// ---------------- problem constants ----------------
#define DIMC   1024
#define DEPTHL 6
#define HEADS  16
#define DHEAD  64
#define NKV    2048
#define NQKV   3072
#define FFD    4096
#define BTOT   32
#define MEDIA  1024
#define NMEDIA (BTOT*MEDIA)          // 32768
#define NLAT   64
#define LROWS  (BTOT*NLAT)           // 2048

typedef __half hf;

// ---------------- scratch ----------------
__device__ __align__(1024) hf    g_xh  [(size_t)NMEDIA*DIMC];
__device__ __align__(1024) hf    g_kvmh[(size_t)DEPTHL*NMEDIA*NKV];
__device__ float g_lat [LROWS*DIMC];
__device__ __align__(1024) hf    g_lnh [LROWS*DIMC];
__device__ __align__(1024) hf    g_qkvh[(size_t)LROWS*NQKV];
__device__ __align__(1024) hf    g_ath [LROWS*DIMC];
__device__ __align__(1024) hf    g_h1h [(size_t)LROWS*FFD];
__device__ float g_bias[DEPTHL*NKV];
__device__ float g_part[(size_t)4*LROWS*DIMC];

// weight planes (single fp16, B-side), chunk-tiled [K/32][N][32]
__device__ __align__(1024) hf g_wqkvT[(size_t)DEPTHL*NQKV*DIMC];
__device__ __align__(1024) hf g_wkvG [(size_t)DEPTHL*NKV*DIMC];
__device__ __align__(1024) hf g_woT  [(size_t)DEPTHL*DIMC*DIMC];
__device__ __align__(1024) hf g_w1T  [(size_t)DEPTHL*FFD*DIMC];
__device__ __align__(1024) hf g_w2T  [(size_t)DEPTHL*DIMC*FFD];

// ---------------- helpers ----------------
__device__ __forceinline__ uint32_t smem_u32(const void* p) {
    return (uint32_t)__cvta_generic_to_shared(p);
}
__device__ __forceinline__ size_t tiled_idx(int row, int k, int nrows) {
    const int kc = k >> 5, kin = k & 31;
    const int q = kin >> 3, b = kin & 7;
    const int qs = q ^ ((row >> 1) & 3);
    return ((size_t)kc * nrows + row) * 32 + qs * 8 + b;
}
__device__ __forceinline__ void bulk_g2s(uint32_t dst, const void* src, uint32_t bytes, uint32_t mbar) {
    asm volatile("cp.async.bulk.shared::cluster.global.mbarrier::complete_tx::bytes [%0], [%1], %2, [%3];"
                 :: "r"(dst), "l"(src), "r"(bytes), "r"(mbar) : "memory");
}
#define MBARRIER_INIT(addr, cnt) \
    asm volatile("mbarrier.init.shared.b64 [%0], %1;" :: "r"(addr), "r"(cnt) : "memory")
#define MBARRIER_EXPECT_TX(addr, tx) \
    asm volatile("mbarrier.arrive.expect_tx.shared.b64 _, [%0], %1;" :: "r"(addr), "r"(tx) : "memory")
#define MBARRIER_WAIT_PARITY(addr, par) do { \
    uint32_t _m = (addr), _p = (par), _d; \
    asm volatile("{\n\t.reg .pred p;\n\t" \
        "mbarrier.try_wait.parity.acquire.cta.shared::cta.b64 p, [%1], %2;\n\t" \
        "selp.b32 %0, 1, 0, p;\n\t}" : "=r"(_d) : "r"(_m), "r"(_p) : "memory"); \
    if (!_d) { \
        asm volatile("{\n\t.reg .pred P1;\n\t" \
            "WL_%=:\n\t" \
            "mbarrier.try_wait.parity.acquire.cta.shared::cta.b64 P1, [%0], %1, 0x989680;\n\t" \
            "@P1 bra.uni WD_%=;\n\tbra.uni WL_%=;\n\tWD_%=:\n\t}" \
            :: "r"(_m), "r"(_p) : "memory"); \
    } } while (0)

__device__ __forceinline__ void ldmx4(uint32_t* r, uint32_t a) {
    asm volatile("ldmatrix.sync.aligned.m8n8.x4.shared.b16 {%0,%1,%2,%3}, [%4];"
                 : "=r"(r[0]), "=r"(r[1]), "=r"(r[2]), "=r"(r[3]) : "r"(a));
}
__device__ __forceinline__ void ldmx4t(uint32_t* r, uint32_t a) {
    asm volatile("ldmatrix.sync.aligned.m8n8.x4.trans.shared.b16 {%0,%1,%2,%3}, [%4];"
                 : "=r"(r[0]), "=r"(r[1]), "=r"(r[2]), "=r"(r[3]) : "r"(a));
}
__device__ __forceinline__ void mma16816(float* d, const uint32_t* a, const uint32_t* b) {
    asm volatile("mma.sync.aligned.m16n8k16.row.col.f32.f16.f16.f32 "
                 "{%0,%1,%2,%3},{%4,%5,%6,%7},{%8,%9},{%0,%1,%2,%3};"
                 : "+f"(d[0]), "+f"(d[1]), "+f"(d[2]), "+f"(d[3])
                 : "r"(a[0]), "r"(a[1]), "r"(a[2]), "r"(a[3]),
                   "r"(b[0]), "r"(b[1]));
}
__device__ __forceinline__ uint32_t bits2(__half2 h) {
    return *reinterpret_cast<uint32_t*>(&h);
}

// ---------------- LayerNorm: fp32 in -> fp32 out and/or tiled fp16 hi plane ----
__global__ void ln_kernel(const float* __restrict__ in,
                          float* __restrict__ outF,
                          hf* __restrict__ outH,
                          const float* __restrict__ g, const float* __restrict__ b,
                          int nrows)
{
    const int row = blockIdx.x;
    const float* x = in + (size_t)row * DIMC;
    float s = 0.f, sq = 0.f;
    for (int c = threadIdx.x; c < DIMC; c += blockDim.x) {
        float v = x[c]; s += v; sq += v * v;
    }
    __shared__ float sh[64];
    #pragma unroll
    for (int o = 16; o > 0; o >>= 1) {
        s  += __shfl_down_sync(0xffffffffu, s,  o);
        sq += __shfl_down_sync(0xffffffffu, sq, o);
    }
    const int wid = threadIdx.x >> 5, lid = threadIdx.x & 31;
    if (lid == 0) { sh[wid] = s; sh[wid + 32] = sq; }
    __syncthreads();
    if (threadIdx.x == 0) {
        float ts = 0.f, tsq = 0.f;
        const int nw = blockDim.x >> 5;
        for (int i = 0; i < nw; i++) { ts += sh[i]; tsq += sh[i + 32]; }
        const float mean = ts * (1.0f / DIMC);
        const float var  = tsq * (1.0f / DIMC) - mean * mean;
        sh[0] = mean; sh[1] = rsqrtf(var + 1e-5f);
    }
    __syncthreads();
    const float mean = sh[0], rstd = sh[1];

    for (int k0 = threadIdx.x * 8; k0 < DIMC; k0 += blockDim.x * 8) {
        float v[8];
        #pragma unroll
        for (int e = 0; e < 8; e++) {
            float t = (x[k0 + e] - mean) * rstd;
            if (g) t = t * g[k0 + e] + b[k0 + e];
            v[e] = t;
        }
        if (outF) {
            float* o = outF + (size_t)row * DIMC + k0;
            #pragma unroll
            for (int e = 0; e < 8; e++) o[e] = v[e];
        }
        if (outH) {
            uint32_t hq[4];
            #pragma unroll
            for (int e = 0; e < 4; e++)
                hq[e] = bits2(__floats2half2_rn(v[2*e], v[2*e+1]));
            *reinterpret_cast<uint4*>(&outH[tiled_idx(row, k0, nrows)]) =
                make_uint4(hq[0], hq[1], hq[2], hq[3]);
        }
    }
}

// ---------------- fused split-K reduce + residual + LayerNorm ----------------
__global__ void __launch_bounds__(128)
lnred_kernel(const float* __restrict__ part, int S,
             const float* __restrict__ latin,
             float* __restrict__ latout,
             float* __restrict__ outF,
             hf* __restrict__ outH,
             const float* __restrict__ g, const float* __restrict__ b)
{
    const int row = blockIdx.x;
    const int tid = threadIdx.x;
    const size_t base = (size_t)row * DIMC + tid * 8;
    float v[8];
    #pragma unroll
    for (int e = 0; e < 8; e++) v[e] = latin[base + e];
    for (int s = 0; s < S; s++) {
        const float* p = part + (size_t)s * LROWS * DIMC + base;
        #pragma unroll
        for (int e = 0; e < 8; e++) v[e] += p[e];
    }
    if (latout) {
        #pragma unroll
        for (int e = 0; e < 8; e++) latout[base + e] = v[e];
    }
    float s1 = 0.f, s2 = 0.f;
    #pragma unroll
    for (int e = 0; e < 8; e++) { s1 += v[e]; s2 += v[e] * v[e]; }
    __shared__ float sh[8];
    #pragma unroll
    for (int o = 16; o > 0; o >>= 1) {
        s1 += __shfl_down_sync(0xffffffffu, s1, o);
        s2 += __shfl_down_sync(0xffffffffu, s2, o);
    }
    const int wid = tid >> 5, lid = tid & 31;
    if (lid == 0) { sh[wid] = s1; sh[wid + 4] = s2; }
    __syncthreads();
    if (tid == 0) {
        float ts = sh[0] + sh[1] + sh[2] + sh[3];
        float tq = sh[4] + sh[5] + sh[6] + sh[7];
        const float mean = ts * (1.0f / DIMC);
        const float var  = tq * (1.0f / DIMC) - mean * mean;
        sh[0] = mean; sh[1] = rsqrtf(var + 1e-5f);
    }
    __syncthreads();
    const float mean = sh[0], rstd = sh[1];
    const int k0 = tid * 8;
    float t[8];
    #pragma unroll
    for (int e = 0; e < 8; e++)
        t[e] = (v[e] - mean) * rstd * g[k0 + e] + b[k0 + e];
    if (outF) {
        float* o = outF + base;
        #pragma unroll
        for (int e = 0; e < 8; e++) o[e] = t[e];
    }
    if (outH) {
        uint32_t hq[4];
        #pragma unroll
        for (int e = 0; e < 4; e++)
            hq[e] = bits2(__floats2half2_rn(t[2*e], t[2*e+1]));
        *reinterpret_cast<uint4*>(&outH[tiled_idx(row, k0, LROWS)]) =
            make_uint4(hq[0], hq[1], hq[2], hq[3]);
    }
}

// ---------------- bias: all layers, k-parallel ----------------
__global__ void bias_kernel(const float* __restrict__ nm_b,
                            const float* __restrict__ wkv, float* __restrict__ out)
{
    const int layer = blockIdx.y;
    const int tid = threadIdx.x;
    const int n  = blockIdx.x * 32 + (tid & 31);
    const int ks = tid >> 5;
    const float* bv = nm_b + (size_t)layer * DIMC;
    const float* W  = wkv  + (size_t)layer * DIMC * NKV;
    float s = 0.f;
    #pragma unroll 4
    for (int k = ks * 128; k < ks * 128 + 128; k++)
        s += bv[k] * __ldg(&W[(size_t)k * NKV + n]);
    __shared__ float red[8][32];
    red[ks][tid & 31] = s;
    __syncthreads();
    if (ks == 0) {
        float t = 0.f;
        #pragma unroll
        for (int i = 0; i < 8; i++) t += red[i][tid & 31];
        out[(size_t)layer * NKV + n] = t;
    }
}

__global__ void init_lat_kernel(const float* __restrict__ latents, float* __restrict__ lat)
{
    const int idx = blockIdx.x * blockDim.x + threadIdx.x;
    lat[idx] = latents[idx & (NLAT * DIMC - 1)];
}

// ---------------- weight transpose + gamma + fp16 quantize (batched over depth) ----
__global__ void wsplit_kernel(const float* __restrict__ W0, const float* __restrict__ g0,
                              hf* __restrict__ T0, int K, int N, int nofs, int ntot)
{
    const int z = blockIdx.z;
    const float* W = W0 + (size_t)z * K * N;
    const float* g = g0 ? g0 + (size_t)z * K : nullptr;
    hf* T = T0 + (size_t)z * ntot * K;
    __shared__ float t[32][33];
    const int n0 = blockIdx.x * 32, k0 = blockIdx.y * 32;
    const int tx = threadIdx.x, ty = threadIdx.y;
    #pragma unroll
    for (int i = 0; i < 4; i++) {
        float v = W[(size_t)(k0 + ty + 8 * i) * N + n0 + tx];
        if (g) v *= g[k0 + ty + 8 * i];
        t[ty + 8 * i][tx] = v;
    }
    __syncthreads();
    #pragma unroll
    for (int i = 0; i < 4; i++) {
        const int n = n0 + ty + 8 * i, k = k0 + tx;
        T[tiled_idx(nofs + n, k, ntot)] = __float2half_rn(t[tx][ty + 8 * i]);
    }
}

// =====================================================================
// 1-term fp16 HMMA GEMM, occ 2, 3 x K64 stages.
// grid.z = layers (lstr*) OR split-K partitions (splitk>1, Cpart).
// =====================================================================
#define NSTG1 3
#define STG1  32768                   // [A c0 8K | A c1 8K | B c0 8K | B c1 8K]
#define G1_SMEM (1024 + NSTG1*STG1)   // 99328

__global__ void __launch_bounds__(256, 2)
gemm1_tc(const hf* __restrict__ Ah, const hf* __restrict__ B0,
         float* __restrict__ Cf, hf* __restrict__ Ch0,
         int M, int N, int K,
         const float* __restrict__ bias0, int dogelu,
         size_t lstrB, size_t lstrC, int lstrBias,
         int splitk, float* __restrict__ Cpart)
{
    extern __shared__ char smem[];
    const uint32_t sb = smem_u32(smem);
    const int tid  = threadIdx.x;
    const int lane = tid & 31;
    const int wid  = tid >> 5;
    const int wm   = wid & 1;
    const int wn   = wid >> 1;
    const int bm   = blockIdx.y * 128;
    const int bn   = blockIdx.x * 128;
    const int z    = blockIdx.z;

    const hf* B = B0;
    hf* Ch = Ch0;
    const float* bias = bias0;
    const int nc = K >> 5;
    int ncl = nc, c0 = 0;
    if (splitk > 1) { ncl = nc / splitk; c0 = z * ncl; }
    else if (z) {
        B += (size_t)z * lstrB;
        if (Ch0) Ch += (size_t)z * lstrC;
        if (bias0) bias += (size_t)z * lstrBias;
    }
    const int nst = ncl >> 1;          // K64 stages (ncl always even, nst >= 4)

    if (tid == 0) {
        #pragma unroll
        for (int s = 0; s < NSTG1; s++) MBARRIER_INIT(sb + 8 * s, 1);
    }
    __syncthreads();

    float acc[4][4][4];
    #pragma unroll
    for (int i = 0; i < 4; i++)
        #pragma unroll
        for (int j = 0; j < 4; j++)
            #pragma unroll
            for (int q = 0; q < 4; q++) acc[i][j][q] = 0.f;

    auto issue = [&](int st) {
        const int slot = st % NSTG1;
        const uint32_t mb  = sb + 8 * slot;
        const uint32_t dst = sb + 1024 + slot * STG1;
        MBARRIER_EXPECT_TX(mb, 32768u);
        #pragma unroll
        for (int half = 0; half < 2; half++) {
            const int gc = c0 + 2 * st + half;
            bulk_g2s(dst + half * 8192,         Ah + ((size_t)gc * M + bm) * 32, 8192, mb);
            bulk_g2s(dst + 16384 + half * 8192, B  + ((size_t)gc * N + bn) * 32, 8192, mb);
        }
    };
    if (tid == 0) { issue(0); issue(1); issue(2); }   // nst >= 4 always

    for (int st = 0; st < nst; st++) {
        const int slot = st % NSTG1;
        MBARRIER_WAIT_PARITY(sb + 8 * slot, (st / NSTG1) & 1);
        const uint32_t base = sb + 1024 + slot * STG1;
        #pragma unroll
        for (int u = 0; u < 4; u++) {
            const int half = u >> 1, s16 = u & 1;
            const uint32_t stA = base + half * 8192;
            const uint32_t stB = base + 16384 + half * 8192;
            uint32_t aH[16], bf[8];
            #pragma unroll
            for (int mi = 0; mi < 4; mi++) {
                const int row = wm * 64 + mi * 16 + (lane & 15);
                const int q   = s16 * 2 + (lane >> 4);
                ldmx4(aH + 4 * mi, stA + row * 64 + ((q ^ ((row >> 1) & 3)) << 4));
            }
            #pragma unroll
            for (int ni = 0; ni < 2; ni++) {
                const int row = wn * 32 + ni * 16 + (lane & 7) + ((lane >> 4) << 3);
                const int q   = s16 * 2 + ((lane >> 3) & 1);
                uint32_t t[4];
                ldmx4(t, stB + row * 64 + ((q ^ ((row >> 1) & 3)) << 4));
                bf[ni*4+0] = t[0]; bf[ni*4+1] = t[1]; bf[ni*4+2] = t[2]; bf[ni*4+3] = t[3];
            }
            #pragma unroll
            for (int mi = 0; mi < 4; mi++)
                #pragma unroll
                for (int j = 0; j < 4; j++)
                    mma16816(acc[mi][j], aH + 4 * mi, bf + 2 * j);
        }
        __syncthreads();
        if (tid == 0 && st + NSTG1 < nst) issue(st + NSTG1);
    }

    if (Cpart) {
        float* P = Cpart + (size_t)z * M * N;
        #pragma unroll
        for (int mi = 0; mi < 4; mi++)
            #pragma unroll
            for (int j = 0; j < 4; j++) {
                const int colb = bn + wn * 32 + j * 8 + (lane & 3) * 2;
                #pragma unroll
                for (int p = 0; p < 2; p++) {
                    const int row = bm + wm * 64 + mi * 16 + (lane >> 2) + 8 * p;
                    *reinterpret_cast<float2*>(&P[(size_t)row * N + colb]) =
                        make_float2(acc[mi][j][p * 2], acc[mi][j][p * 2 + 1]);
                }
            }
        return;
    }
    #pragma unroll
    for (int mi = 0; mi < 4; mi++) {
        #pragma unroll
        for (int j = 0; j < 4; j++) {
            const int colb = bn + wn * 32 + j * 8 + (lane & 3) * 2;
            #pragma unroll
            for (int p = 0; p < 2; p++) {
                const int row = bm + wm * 64 + mi * 16 + (lane >> 2) + 8 * p;
                float v0 = acc[mi][j][p * 2], v1 = acc[mi][j][p * 2 + 1];
                if (bias) { v0 += bias[colb]; v1 += bias[colb + 1]; }
                if (dogelu) {
                    v0 = 0.5f * v0 * (1.f + erff(v0 * 0.70710678118654752f));
                    v1 = 0.5f * v1 * (1.f + erff(v1 * 0.70710678118654752f));
                }
                if (Cf) *reinterpret_cast<float2*>(&Cf[(size_t)row * N + colb]) = make_float2(v0, v1);
                if (Ch) {
                    const __half2 h = __floats2half2_rn(v0, v1);
                    *reinterpret_cast<uint32_t*>(&Ch[tiled_idx(row, colb, M)]) = bits2(h);
                }
            }
        }
    }
}

// =====================================================================
// FA2 attention — single-plane Q (register P, occ 3).
// =====================================================================
#define A_OFFQ  1024
#define A_OFFKV (A_OFFQ + 8192)
#define A_SMEM  (A_OFFKV + 32768)     // 41984

__global__ void __launch_bounds__(128, 3)
attn_tc(const hf* __restrict__ QKVh,
        const hf* __restrict__ Kmh,
        hf* __restrict__ OH)
{
    extern __shared__ char smem[];
    const uint32_t sb = smem_u32(smem);
    const int bt  = blockIdx.x >> 4;
    const int h   = blockIdx.x & 15;
    const int tid = threadIdx.x;
    const int lane = tid & 31;
    const int wq   = tid >> 5;

    if (tid == 0) { MBARRIER_INIT(sb, 1); MBARRIER_INIT(sb + 8, 1); }

    #pragma unroll
    for (int seg = 0; seg < 2; seg++) {
        const hf* src = QKVh + ((size_t)(2 * h + seg) * LROWS + bt * 64) * 32;
        #pragma unroll
        for (int it = 0; it < 2; it++) {
            const int idx = tid + it * 128;
            const uint4 v = reinterpret_cast<const uint4*>(src)[idx];
            *reinterpret_cast<uint4*>(smem + A_OFFQ + seg * 4096 + idx * 16) = v;
        }
    }
    __syncthreads();

    auto issueKV = [&](int t) {
        const int st = t & 1;
        const uint32_t mb = sb + 8 * st;
        const uint32_t dst = sb + A_OFFKV + st * 16384;
        MBARRIER_EXPECT_TX(mb, 16384u);
        const hf* PH; size_t rbase, nr; int kcK, kcV;
        if (t < 16) { PH = Kmh;  rbase = (size_t)bt * 1024 + t * 64; nr = NMEDIA; kcK = 2*h;      kcV = 32 + 2*h; }
        else        { PH = QKVh; rbase = (size_t)bt * 64;            nr = LROWS;  kcK = 32 + 2*h; kcV = 64 + 2*h; }
        bulk_g2s(dst,          PH + ((size_t)kcK * nr + rbase) * 32,       4096, mb);
        bulk_g2s(dst +  4096,  PH + ((size_t)(kcK + 1) * nr + rbase) * 32, 4096, mb);
        bulk_g2s(dst +  8192,  PH + ((size_t)kcV * nr + rbase) * 32,       4096, mb);
        bulk_g2s(dst + 12288,  PH + ((size_t)(kcV + 1) * nr + rbase) * 32, 4096, mb);
    };
    if (tid == 0) issueKV(0);

    uint32_t qH[4][4];
    #pragma unroll
    for (int s = 0; s < 4; s++) {
        const int row = wq * 16 + (lane & 15);
        const int qq = (((s & 1) * 2 + (lane >> 4)) ^ ((row >> 1) & 3));
        ldmx4(qH[s], sb + A_OFFQ + (s >> 1) * 4096 + row * 64 + (qq << 4));
    }

    float mrow[2] = {-INFINITY, -INFINITY};
    float lrow[2] = {0.f, 0.f};
    float acc[4][2][4];
    #pragma unroll
    for (int d = 0; d < 4; d++)
        #pragma unroll
        for (int j = 0; j < 2; j++)
            #pragma unroll
            for (int q = 0; q < 4; q++) acc[d][j][q] = 0.f;

    for (int t = 0; t < 17; t++) {
        if (tid == 0 && t + 1 < 17) issueKV(t + 1);
        MBARRIER_WAIT_PARITY(sb + 8 * (t & 1), (t >> 1) & 1);
        const uint32_t kb = sb + A_OFFKV + (t & 1) * 16384;

        float sc[4][2][4];
        #pragma unroll
        for (int kg = 0; kg < 4; kg++)
            #pragma unroll
            for (int j = 0; j < 2; j++)
                #pragma unroll
                for (int q = 0; q < 4; q++) sc[kg][j][q] = 0.f;
        #pragma unroll
        for (int s = 0; s < 4; s++) {
            #pragma unroll
            for (int kg = 0; kg < 4; kg++) {
                const int row = kg * 16 + (lane & 7) + ((lane >> 4) << 3);
                const int qq = (((s & 1) * 2 + ((lane >> 3) & 1)) ^ ((row >> 1) & 3));
                uint32_t tB[4];
                ldmx4(tB, kb + (s >> 1) * 4096 + row * 64 + (qq << 4));
                uint32_t b0[2] = {tB[0], tB[1]}, b1[2] = {tB[2], tB[3]};
                mma16816(sc[kg][0], qH[s], b0);
                mma16816(sc[kg][1], qH[s], b1);
            }
        }
        #pragma unroll
        for (int kg = 0; kg < 4; kg++)
            #pragma unroll
            for (int j = 0; j < 2; j++)
                #pragma unroll
                for (int q = 0; q < 4; q++) sc[kg][j][q] *= 0.125f;

        #pragma unroll
        for (int p = 0; p < 2; p++) {
            float m = -INFINITY;
            #pragma unroll
            for (int kg = 0; kg < 4; kg++)
                #pragma unroll
                for (int j = 0; j < 2; j++) {
                    m = fmaxf(m, sc[kg][j][p * 2]);
                    m = fmaxf(m, sc[kg][j][p * 2 + 1]);
                }
            m = fmaxf(m, __shfl_xor_sync(0xffffffffu, m, 1));
            m = fmaxf(m, __shfl_xor_sync(0xffffffffu, m, 2));
            const float mnew = fmaxf(mrow[p], m);
            const float fac = __expf(mrow[p] - mnew);
            float sum = 0.f;
            #pragma unroll
            for (int kg = 0; kg < 4; kg++)
                #pragma unroll
                for (int j = 0; j < 2; j++) {
                    const float e0 = __expf(sc[kg][j][p * 2]     - mnew);
                    const float e1 = __expf(sc[kg][j][p * 2 + 1] - mnew);
                    sc[kg][j][p * 2] = e0; sc[kg][j][p * 2 + 1] = e1;
                    sum += e0 + e1;
                }
            sum += __shfl_xor_sync(0xffffffffu, sum, 1);
            sum += __shfl_xor_sync(0xffffffffu, sum, 2);
            lrow[p] = lrow[p] * fac + sum;
            mrow[p] = mnew;
            #pragma unroll
            for (int d = 0; d < 4; d++)
                #pragma unroll
                for (int j = 0; j < 2; j++) {
                    acc[d][j][p * 2]     *= fac;
                    acc[d][j][p * 2 + 1] *= fac;
                }
        }

        #pragma unroll
        for (int kg = 0; kg < 4; kg++) {
            uint32_t pa[4];
            pa[0] = bits2(__floats2half2_rn(sc[kg][0][0], sc[kg][0][1]));
            pa[1] = bits2(__floats2half2_rn(sc[kg][0][2], sc[kg][0][3]));
            pa[2] = bits2(__floats2half2_rn(sc[kg][1][0], sc[kg][1][1]));
            pa[3] = bits2(__floats2half2_rn(sc[kg][1][2], sc[kg][1][3]));
            #pragma unroll
            for (int dg = 0; dg < 4; dg++) {
                const int key  = kg * 16 + (lane & 15);
                const int dinb = dg * 16 + ((lane >> 4) << 3);
                const int kcv  = dinb >> 5, din = dinb & 31;
                const int qq   = ((din >> 3) ^ ((key >> 1) & 3));
                uint32_t tV[4];
                ldmx4t(tV, kb + 8192 + kcv * 4096 + key * 64 + (qq << 4));
                uint32_t v0[2] = {tV[0], tV[1]}, v1[2] = {tV[2], tV[3]};
                mma16816(acc[dg][0], pa, v0);
                mma16816(acc[dg][1], pa, v1);
            }
        }
        __syncthreads();
    }

    #pragma unroll
    for (int p = 0; p < 2; p++) {
        const float inv = 1.0f / lrow[p];
        const int row = bt * 64 + wq * 16 + (lane >> 2) + 8 * p;
        #pragma unroll
        for (int dg = 0; dg < 4; dg++)
            #pragma unroll
            for (int j = 0; j < 2; j++) {
                const int col = h * 64 + dg * 16 + j * 8 + (lane & 3) * 2;
                const __half2 hh = __floats2half2_rn(acc[dg][j][p * 2] * inv,
                                                     acc[dg][j][p * 2 + 1] * inv);
                *reinterpret_cast<uint32_t*>(&OH[tiled_idx(row, col, LROWS)]) = bits2(hh);
            }
    }
}

// ---------------- orchestration (dual-stream graph fork) ----------------
extern "C" void kernel_launch(void* const* d_in, const int* in_sizes, int n_in,
                              void* d_out, int out_size)
{
    (void)in_sizes; (void)n_in; (void)out_size;
    const float* x       = (const float*)d_in[0];
    const float* latents = (const float*)d_in[1];
    const float* nm_g    = (const float*)d_in[2];
    const float* nm_b    = (const float*)d_in[3];
    const float* nl_g    = (const float*)d_in[4];
    const float* nl_b    = (const float*)d_in[5];
    const float* wq      = (const float*)d_in[6];
    const float* wkv     = (const float*)d_in[7];
    const float* wo      = (const float*)d_in[8];
    const float* ff_g    = (const float*)d_in[9];
    const float* ff_b    = (const float*)d_in[10];
    const float* w1      = (const float*)d_in[11];
    const float* w2      = (const float*)d_in[12];
    const float* fin_g   = (const float*)d_in[13];
    const float* fin_b   = (const float*)d_in[14];
    float* out = (float*)d_out;

    hf *xh, *kvmh, *lnh, *qkvh, *ath, *h1h;
    float *lat, *bias, *part;
    cudaGetSymbolAddress((void**)&xh,   g_xh);
    cudaGetSymbolAddress((void**)&kvmh, g_kvmh);
    cudaGetSymbolAddress((void**)&lat,  g_lat);
    cudaGetSymbolAddress((void**)&lnh,  g_lnh);
    cudaGetSymbolAddress((void**)&qkvh, g_qkvh);
    cudaGetSymbolAddress((void**)&ath,  g_ath);
    cudaGetSymbolAddress((void**)&h1h,  g_h1h);
    cudaGetSymbolAddress((void**)&bias, g_bias); cudaGetSymbolAddress((void**)&part, g_part);

    hf *wqkvT, *wkvG, *woT, *w1T, *w2T;
    cudaGetSymbolAddress((void**)&wqkvT, g_wqkvT);
    cudaGetSymbolAddress((void**)&wkvG,  g_wkvG);
    cudaGetSymbolAddress((void**)&woT,   g_woT);
    cudaGetSymbolAddress((void**)&w1T,   g_w1T);
    cudaGetSymbolAddress((void**)&w2T,   g_w2T);

    cudaFuncSetAttribute(gemm1_tc, cudaFuncAttributeMaxDynamicSharedMemorySize, G1_SMEM);
    cudaFuncSetAttribute(attn_tc,  cudaFuncAttributeMaxDynamicSharedMemorySize, A_SMEM);
    const dim3 tb(32, 8);

    cudaStream_t s2;
    cudaStreamCreate(&s2);
    cudaEvent_t eFork, eKv[DEPTHL];
    cudaEventCreateWithFlags(&eFork, cudaEventDisableTiming);
    for (int i = 0; i < DEPTHL; i++) cudaEventCreateWithFlags(&eKv[i], cudaEventDisableTiming);

    // ---- kv-path prerequisites on main stream ----
    wsplit_kernel<<<dim3(NKV/32, DIMC/32, DEPTHL), tb>>>(wkv, nm_g, wkvG, DIMC, NKV, 0, NKV);
    bias_kernel<<<dim3(NKV/32, DEPTHL), 256>>>(nm_b, wkv, bias);
    ln_kernel<<<NMEDIA, 128>>>(x, nullptr, xh, nullptr, nullptr, NMEDIA);
    cudaEventRecord(eFork, 0);
    cudaStreamWaitEvent(s2, eFork, 0);

    // ---- kv_media per layer on stream 2 ----
    for (int i = 0; i < DEPTHL; i++) {
        gemm1_tc<<<dim3(NKV/128, NMEDIA/128), 256, G1_SMEM, s2>>>(
            xh, wkvG + (size_t)i*NKV*DIMC, nullptr, kvmh + (size_t)i*NMEDIA*NKV,
            NMEDIA, NKV, DIMC, bias + (size_t)i*NKV, 0,
            0, 0, 0, 1, nullptr);
        cudaEventRecord(eKv[i], s2);
    }

    // ---- latent-path prep on main stream ----
    wsplit_kernel<<<dim3(DIMC/32, DIMC/32, DEPTHL), tb>>>(wq,  nullptr, wqkvT, DIMC, DIMC, 0,    NQKV);
    wsplit_kernel<<<dim3(NKV/32,  DIMC/32, DEPTHL), tb>>>(wkv, nullptr, wqkvT, DIMC, NKV,  DIMC, NQKV);
    wsplit_kernel<<<dim3(DIMC/32, DIMC/32, DEPTHL), tb>>>(wo,  nullptr, woT,   DIMC, DIMC, 0,    DIMC);
    wsplit_kernel<<<dim3(FFD/32,  DIMC/32, DEPTHL), tb>>>(w1,  nullptr, w1T,   DIMC, FFD,  0,    FFD);
    wsplit_kernel<<<dim3(DIMC/32, FFD/32,  DEPTHL), tb>>>(w2,  nullptr, w2T,   FFD,  DIMC, 0,    DIMC);
    init_lat_kernel<<<(LROWS * DIMC) / 256, 256>>>(latents, lat);
    ln_kernel<<<LROWS, 128>>>(lat, nullptr, lnh, nl_g, nl_b, LROWS);

    for (int i = 0; i < DEPTHL; i++) {
        gemm1_tc<<<dim3(NQKV/128, LROWS/128), 256, G1_SMEM>>>(
            lnh, wqkvT + (size_t)i*NQKV*DIMC,
            nullptr, qkvh, LROWS, NQKV, DIMC, nullptr, 0,
            0, 0, 0, 1, nullptr);
        cudaStreamWaitEvent(0, eKv[i], 0);
        attn_tc<<<BTOT * HEADS, 128, A_SMEM>>>(
            qkvh, kvmh + (size_t)i*NMEDIA*NKV, ath);
        gemm1_tc<<<dim3(DIMC/128, LROWS/128, 2), 256, G1_SMEM>>>(
            ath, woT + (size_t)i*DIMC*DIMC,
            nullptr, nullptr, LROWS, DIMC, DIMC, nullptr, 0,
            0, 0, 0, 2, part);
        lnred_kernel<<<LROWS, 128>>>(part, 2, lat, lat, nullptr, lnh,
                                     ff_g + (size_t)i*DIMC, ff_b + (size_t)i*DIMC);
        gemm1_tc<<<dim3(FFD/128, LROWS/128), 256, G1_SMEM>>>(
            lnh, w1T + (size_t)i*FFD*DIMC,
            nullptr, h1h, LROWS, FFD, DIMC, nullptr, 1,
            0, 0, 0, 1, nullptr);
        gemm1_tc<<<dim3(DIMC/128, LROWS/128, 4), 256, G1_SMEM>>>(
            h1h, w2T + (size_t)i*DIMC*FFD,
            nullptr, nullptr, LROWS, DIMC, FFD, nullptr, 0,
            0, 0, 0, 4, part);
        if (i + 1 < DEPTHL) {
            lnred_kernel<<<LROWS, 128>>>(part, 4, lat, lat, nullptr, lnh,
                                         nl_g + (size_t)(i+1)*DIMC, nl_b + (size_t)(i+1)*DIMC);
        } else {
            lnred_kernel<<<LROWS, 128>>>(part, 4, lat, nullptr, out, nullptr,
                                         fin_g, fin_b);
        }
    }
}

// round 16
// speedup vs baseline: 1.0106x; 1.0106x over previous
#include <cuda_runtime.h>
#include <cuda_fp16.h>
#include <math.h>
#include <stdint.h>

// ---------------- problem constants ----------------
#define DIMC   1024
#define DEPTHL 6
#define HEADS  16
#define DHEAD  64
#define NKV    2048
#define NQKV   3072
#define FFD    4096
#define BTOT   32
#define MEDIA  1024
#define NMEDIA (BTOT*MEDIA)          // 32768
#define NLAT   64
#define LROWS  (BTOT*NLAT)           // 2048

typedef __half hf;

// ---------------- scratch ----------------
__device__ __align__(1024) hf    g_xh  [(size_t)NMEDIA*DIMC];
__device__ __align__(1024) hf    g_kvmh[(size_t)DEPTHL*NMEDIA*NKV];
__device__ float g_lat [LROWS*DIMC];
__device__ __align__(1024) hf    g_lnh [LROWS*DIMC];
__device__ __align__(1024) hf    g_qkvh[(size_t)LROWS*NQKV];
__device__ __align__(1024) hf    g_ath [LROWS*DIMC];
__device__ __align__(1024) hf    g_h1h [(size_t)LROWS*FFD];
__device__ float g_bias[DEPTHL*NKV];
__device__ float g_part[(size_t)4*LROWS*DIMC];

// weight planes (single fp16, B-side), chunk-tiled [K/32][N][32]
__device__ __align__(1024) hf g_wqkvT[(size_t)DEPTHL*NQKV*DIMC];
__device__ __align__(1024) hf g_wkvG [(size_t)DEPTHL*NKV*DIMC];
__device__ __align__(1024) hf g_woT  [(size_t)DEPTHL*DIMC*DIMC];
__device__ __align__(1024) hf g_w1T  [(size_t)DEPTHL*FFD*DIMC];
__device__ __align__(1024) hf g_w2T  [(size_t)DEPTHL*DIMC*FFD];

// ---------------- helpers ----------------
__device__ __forceinline__ uint32_t smem_u32(const void* p) {
    return (uint32_t)__cvta_generic_to_shared(p);
}
__device__ __forceinline__ size_t tiled_idx(int row, int k, int nrows) {
    const int kc = k >> 5, kin = k & 31;
    const int q = kin >> 3, b = kin & 7;
    const int qs = q ^ ((row >> 1) & 3);
    return ((size_t)kc * nrows + row) * 32 + qs * 8 + b;
}
__device__ __forceinline__ void bulk_g2s(uint32_t dst, const void* src, uint32_t bytes, uint32_t mbar) {
    asm volatile("cp.async.bulk.shared::cluster.global.mbarrier::complete_tx::bytes [%0], [%1], %2, [%3];"
                 :: "r"(dst), "l"(src), "r"(bytes), "r"(mbar) : "memory");
}
#define MBARRIER_INIT(addr, cnt) \
    asm volatile("mbarrier.init.shared.b64 [%0], %1;" :: "r"(addr), "r"(cnt) : "memory")
#define MBARRIER_EXPECT_TX(addr, tx) \
    asm volatile("mbarrier.arrive.expect_tx.shared.b64 _, [%0], %1;" :: "r"(addr), "r"(tx) : "memory")
#define MBARRIER_WAIT_PARITY(addr, par) do { \
    uint32_t _m = (addr), _p = (par), _d; \
    asm volatile("{\n\t.reg .pred p;\n\t" \
        "mbarrier.try_wait.parity.acquire.cta.shared::cta.b64 p, [%1], %2;\n\t" \
        "selp.b32 %0, 1, 0, p;\n\t}" : "=r"(_d) : "r"(_m), "r"(_p) : "memory"); \
    if (!_d) { \
        asm volatile("{\n\t.reg .pred P1;\n\t" \
            "WL_%=:\n\t" \
            "mbarrier.try_wait.parity.acquire.cta.shared::cta.b64 P1, [%0], %1, 0x989680;\n\t" \
            "@P1 bra.uni WD_%=;\n\tbra.uni WL_%=;\n\tWD_%=:\n\t}" \
            :: "r"(_m), "r"(_p) : "memory"); \
    } } while (0)

__device__ __forceinline__ void ldmx4(uint32_t* r, uint32_t a) {
    asm volatile("ldmatrix.sync.aligned.m8n8.x4.shared.b16 {%0,%1,%2,%3}, [%4];"
                 : "=r"(r[0]), "=r"(r[1]), "=r"(r[2]), "=r"(r[3]) : "r"(a));
}
__device__ __forceinline__ void ldmx4t(uint32_t* r, uint32_t a) {
    asm volatile("ldmatrix.sync.aligned.m8n8.x4.trans.shared.b16 {%0,%1,%2,%3}, [%4];"
                 : "=r"(r[0]), "=r"(r[1]), "=r"(r[2]), "=r"(r[3]) : "r"(a));
}
__device__ __forceinline__ void mma16816(float* d, const uint32_t* a, const uint32_t* b) {
    asm volatile("mma.sync.aligned.m16n8k16.row.col.f32.f16.f16.f32 "
                 "{%0,%1,%2,%3},{%4,%5,%6,%7},{%8,%9},{%0,%1,%2,%3};"
                 : "+f"(d[0]), "+f"(d[1]), "+f"(d[2]), "+f"(d[3])
                 : "r"(a[0]), "r"(a[1]), "r"(a[2]), "r"(a[3]),
                   "r"(b[0]), "r"(b[1]));
}
__device__ __forceinline__ uint32_t bits2(__half2 h) {
    return *reinterpret_cast<uint32_t*>(&h);
}

// ---------------- LayerNorm: fp32 in -> fp32 out and/or tiled fp16 hi plane ----
__global__ void ln_kernel(const float* __restrict__ in,
                          float* __restrict__ outF,
                          hf* __restrict__ outH,
                          const float* __restrict__ g, const float* __restrict__ b,
                          int nrows)
{
    const int row = blockIdx.x;
    const float* x = in + (size_t)row * DIMC;
    float s = 0.f, sq = 0.f;
    for (int c = threadIdx.x; c < DIMC; c += blockDim.x) {
        float v = x[c]; s += v; sq += v * v;
    }
    __shared__ float sh[64];
    #pragma unroll
    for (int o = 16; o > 0; o >>= 1) {
        s  += __shfl_down_sync(0xffffffffu, s,  o);
        sq += __shfl_down_sync(0xffffffffu, sq, o);
    }
    const int wid = threadIdx.x >> 5, lid = threadIdx.x & 31;
    if (lid == 0) { sh[wid] = s; sh[wid + 32] = sq; }
    __syncthreads();
    if (threadIdx.x == 0) {
        float ts = 0.f, tsq = 0.f;
        const int nw = blockDim.x >> 5;
        for (int i = 0; i < nw; i++) { ts += sh[i]; tsq += sh[i + 32]; }
        const float mean = ts * (1.0f / DIMC);
        const float var  = tsq * (1.0f / DIMC) - mean * mean;
        sh[0] = mean; sh[1] = rsqrtf(var + 1e-5f);
    }
    __syncthreads();
    const float mean = sh[0], rstd = sh[1];

    for (int k0 = threadIdx.x * 8; k0 < DIMC; k0 += blockDim.x * 8) {
        float v[8];
        #pragma unroll
        for (int e = 0; e < 8; e++) {
            float t = (x[k0 + e] - mean) * rstd;
            if (g) t = t * g[k0 + e] + b[k0 + e];
            v[e] = t;
        }
        if (outF) {
            float* o = outF + (size_t)row * DIMC + k0;
            #pragma unroll
            for (int e = 0; e < 8; e++) o[e] = v[e];
        }
        if (outH) {
            uint32_t hq[4];
            #pragma unroll
            for (int e = 0; e < 4; e++)
                hq[e] = bits2(__floats2half2_rn(v[2*e], v[2*e+1]));
            *reinterpret_cast<uint4*>(&outH[tiled_idx(row, k0, nrows)]) =
                make_uint4(hq[0], hq[1], hq[2], hq[3]);
        }
    }
}

// ---------------- fused split-K reduce + residual + LayerNorm ----------------
__global__ void __launch_bounds__(128)
lnred_kernel(const float* __restrict__ part, int S,
             const float* __restrict__ latin,
             float* __restrict__ latout,
             float* __restrict__ outF,
             hf* __restrict__ outH,
             const float* __restrict__ g, const float* __restrict__ b)
{
    const int row = blockIdx.x;
    const int tid = threadIdx.x;
    const size_t base = (size_t)row * DIMC + tid * 8;
    float v[8];
    #pragma unroll
    for (int e = 0; e < 8; e++) v[e] = latin[base + e];
    for (int s = 0; s < S; s++) {
        const float* p = part + (size_t)s * LROWS * DIMC + base;
        #pragma unroll
        for (int e = 0; e < 8; e++) v[e] += p[e];
    }
    if (latout) {
        #pragma unroll
        for (int e = 0; e < 8; e++) latout[base + e] = v[e];
    }
    float s1 = 0.f, s2 = 0.f;
    #pragma unroll
    for (int e = 0; e < 8; e++) { s1 += v[e]; s2 += v[e] * v[e]; }
    __shared__ float sh[8];
    #pragma unroll
    for (int o = 16; o > 0; o >>= 1) {
        s1 += __shfl_down_sync(0xffffffffu, s1, o);
        s2 += __shfl_down_sync(0xffffffffu, s2, o);
    }
    const int wid = tid >> 5, lid = tid & 31;
    if (lid == 0) { sh[wid] = s1; sh[wid + 4] = s2; }
    __syncthreads();
    if (tid == 0) {
        float ts = sh[0] + sh[1] + sh[2] + sh[3];
        float tq = sh[4] + sh[5] + sh[6] + sh[7];
        const float mean = ts * (1.0f / DIMC);
        const float var  = tq * (1.0f / DIMC) - mean * mean;
        sh[0] = mean; sh[1] = rsqrtf(var + 1e-5f);
    }
    __syncthreads();
    const float mean = sh[0], rstd = sh[1];
    const int k0 = tid * 8;
    float t[8];
    #pragma unroll
    for (int e = 0; e < 8; e++)
        t[e] = (v[e] - mean) * rstd * g[k0 + e] + b[k0 + e];
    if (outF) {
        float* o = outF + base;
        #pragma unroll
        for (int e = 0; e < 8; e++) o[e] = t[e];
    }
    if (outH) {
        uint32_t hq[4];
        #pragma unroll
        for (int e = 0; e < 4; e++)
            hq[e] = bits2(__floats2half2_rn(t[2*e], t[2*e+1]));
        *reinterpret_cast<uint4*>(&outH[tiled_idx(row, k0, LROWS)]) =
            make_uint4(hq[0], hq[1], hq[2], hq[3]);
    }
}

// ---------------- bias: all layers, k-parallel ----------------
__global__ void bias_kernel(const float* __restrict__ nm_b,
                            const float* __restrict__ wkv, float* __restrict__ out)
{
    const int layer = blockIdx.y;
    const int tid = threadIdx.x;
    const int n  = blockIdx.x * 32 + (tid & 31);
    const int ks = tid >> 5;
    const float* bv = nm_b + (size_t)layer * DIMC;
    const float* W  = wkv  + (size_t)layer * DIMC * NKV;
    float s = 0.f;
    #pragma unroll 4
    for (int k = ks * 128; k < ks * 128 + 128; k++)
        s += bv[k] * __ldg(&W[(size_t)k * NKV + n]);
    __shared__ float red[8][32];
    red[ks][tid & 31] = s;
    __syncthreads();
    if (ks == 0) {
        float t = 0.f;
        #pragma unroll
        for (int i = 0; i < 8; i++) t += red[i][tid & 31];
        out[(size_t)layer * NKV + n] = t;
    }
}

__global__ void init_lat_kernel(const float* __restrict__ latents, float* __restrict__ lat)
{
    const int idx = blockIdx.x * blockDim.x + threadIdx.x;
    lat[idx] = latents[idx & (NLAT * DIMC - 1)];
}

// ---------------- weight transpose + gamma + fp16 quantize (batched over depth) ----
__global__ void wsplit_kernel(const float* __restrict__ W0, const float* __restrict__ g0,
                              hf* __restrict__ T0, int K, int N, int nofs, int ntot)
{
    const int z = blockIdx.z;
    const float* W = W0 + (size_t)z * K * N;
    const float* g = g0 ? g0 + (size_t)z * K : nullptr;
    hf* T = T0 + (size_t)z * ntot * K;
    __shared__ float t[32][33];
    const int n0 = blockIdx.x * 32, k0 = blockIdx.y * 32;
    const int tx = threadIdx.x, ty = threadIdx.y;
    #pragma unroll
    for (int i = 0; i < 4; i++) {
        float v = W[(size_t)(k0 + ty + 8 * i) * N + n0 + tx];
        if (g) v *= g[k0 + ty + 8 * i];
        t[ty + 8 * i][tx] = v;
    }
    __syncthreads();
    #pragma unroll
    for (int i = 0; i < 4; i++) {
        const int n = n0 + ty + 8 * i, k = k0 + tx;
        T[tiled_idx(nofs + n, k, ntot)] = __float2half_rn(t[tx][ty + 8 * i]);
    }
}

// =====================================================================
// 1-term fp16 HMMA GEMM, occ 2, 2 x K64 stages, phase-staggered K order.
// Co-resident CTAs visit K-stages with a half-ring offset so their
// mbarrier/bar.sync stalls interleave with the partner's MMA bursts.
// grid.z = layers (lstr*) OR split-K partitions (splitk>1, Cpart).
// =====================================================================
#define NSTG1 2
#define STG1  32768                   // [A c0 8K | A c1 8K | B c0 8K | B c1 8K]
#define G1_SMEM (1024 + NSTG1*STG1)   // 66560

__global__ void __launch_bounds__(256, 2)
gemm1_tc(const hf* __restrict__ Ah, const hf* __restrict__ B0,
         float* __restrict__ Cf, hf* __restrict__ Ch0,
         int M, int N, int K,
         const float* __restrict__ bias0, int dogelu,
         size_t lstrB, size_t lstrC, int lstrBias,
         int splitk, float* __restrict__ Cpart)
{
    extern __shared__ char smem[];
    const uint32_t sb = smem_u32(smem);
    const int tid  = threadIdx.x;
    const int lane = tid & 31;
    const int wid  = tid >> 5;
    const int wm   = wid & 1;
    const int wn   = wid >> 1;
    const int bm   = blockIdx.y * 128;
    const int bn   = blockIdx.x * 128;
    const int z    = blockIdx.z;

    const hf* B = B0;
    hf* Ch = Ch0;
    const float* bias = bias0;
    const int nc = K >> 5;
    int ncl = nc, c0 = 0;
    if (splitk > 1) { ncl = nc / splitk; c0 = z * ncl; }
    else if (z) {
        B += (size_t)z * lstrB;
        if (Ch0) Ch += (size_t)z * lstrC;
        if (bias0) bias += (size_t)z * lstrBias;
    }
    const int nst = ncl >> 1;          // K64 stages; nst in {4,8,16} (pow2)

    // phase offset: co-resident CTAs (lin and lin+148 at occ 2) get opposite
    // half-ring starting points in K. Pure reassociation of fp32 accumulation.
    const int lin   = (int)(blockIdx.x + gridDim.x * (blockIdx.y + gridDim.y * blockIdx.z));
    const int phase = ((lin / 148) & 1) * (nst >> 1);

    if (tid == 0) {
        #pragma unroll
        for (int s = 0; s < NSTG1; s++) MBARRIER_INIT(sb + 8 * s, 1);
    }
    __syncthreads();

    float acc[4][4][4];
    #pragma unroll
    for (int i = 0; i < 4; i++)
        #pragma unroll
        for (int j = 0; j < 4; j++)
            #pragma unroll
            for (int q = 0; q < 4; q++) acc[i][j][q] = 0.f;

    // issue stage si (sequential pipeline slot) loading permuted chunk pair
    auto issue = [&](int si) {
        const int stp = (si + phase) & (nst - 1);     // permuted K-stage
        const uint32_t mb  = sb + 8 * (si & 1);
        const uint32_t dst = sb + 1024 + (si & 1) * STG1;
        MBARRIER_EXPECT_TX(mb, 32768u);
        #pragma unroll
        for (int half = 0; half < 2; half++) {
            const int gc = c0 + 2 * stp + half;
            bulk_g2s(dst + half * 8192,         Ah + ((size_t)gc * M + bm) * 32, 8192, mb);
            bulk_g2s(dst + 16384 + half * 8192, B  + ((size_t)gc * N + bn) * 32, 8192, mb);
        }
    };
    if (tid == 0) { issue(0); issue(1); }   // nst >= 4 always

    for (int si = 0; si < nst; si++) {
        MBARRIER_WAIT_PARITY(sb + 8 * (si & 1), (si >> 1) & 1);
        const uint32_t base = sb + 1024 + (si & 1) * STG1;
        #pragma unroll
        for (int u = 0; u < 4; u++) {
            const int half = u >> 1, s16 = u & 1;
            const uint32_t stA = base + half * 8192;
            const uint32_t stB = base + 16384 + half * 8192;
            uint32_t aH[16], bf[8];
            #pragma unroll
            for (int mi = 0; mi < 4; mi++) {
                const int row = wm * 64 + mi * 16 + (lane & 15);
                const int q   = s16 * 2 + (lane >> 4);
                ldmx4(aH + 4 * mi, stA + row * 64 + ((q ^ ((row >> 1) & 3)) << 4));
            }
            #pragma unroll
            for (int ni = 0; ni < 2; ni++) {
                const int row = wn * 32 + ni * 16 + (lane & 7) + ((lane >> 4) << 3);
                const int q   = s16 * 2 + ((lane >> 3) & 1);
                uint32_t t[4];
                ldmx4(t, stB + row * 64 + ((q ^ ((row >> 1) & 3)) << 4));
                bf[ni*4+0] = t[0]; bf[ni*4+1] = t[1]; bf[ni*4+2] = t[2]; bf[ni*4+3] = t[3];
            }
            #pragma unroll
            for (int mi = 0; mi < 4; mi++)
                #pragma unroll
                for (int j = 0; j < 4; j++)
                    mma16816(acc[mi][j], aH + 4 * mi, bf + 2 * j);
        }
        __syncthreads();
        if (tid == 0 && si + NSTG1 < nst) issue(si + NSTG1);
    }

    if (Cpart) {
        float* P = Cpart + (size_t)z * M * N;
        #pragma unroll
        for (int mi = 0; mi < 4; mi++)
            #pragma unroll
            for (int j = 0; j < 4; j++) {
                const int colb = bn + wn * 32 + j * 8 + (lane & 3) * 2;
                #pragma unroll
                for (int p = 0; p < 2; p++) {
                    const int row = bm + wm * 64 + mi * 16 + (lane >> 2) + 8 * p;
                    *reinterpret_cast<float2*>(&P[(size_t)row * N + colb]) =
                        make_float2(acc[mi][j][p * 2], acc[mi][j][p * 2 + 1]);
                }
            }
        return;
    }
    #pragma unroll
    for (int mi = 0; mi < 4; mi++) {
        #pragma unroll
        for (int j = 0; j < 4; j++) {
            const int colb = bn + wn * 32 + j * 8 + (lane & 3) * 2;
            #pragma unroll
            for (int p = 0; p < 2; p++) {
                const int row = bm + wm * 64 + mi * 16 + (lane >> 2) + 8 * p;
                float v0 = acc[mi][j][p * 2], v1 = acc[mi][j][p * 2 + 1];
                if (bias) { v0 += bias[colb]; v1 += bias[colb + 1]; }
                if (dogelu) {
                    v0 = 0.5f * v0 * (1.f + erff(v0 * 0.70710678118654752f));
                    v1 = 0.5f * v1 * (1.f + erff(v1 * 0.70710678118654752f));
                }
                if (Cf) *reinterpret_cast<float2*>(&Cf[(size_t)row * N + colb]) = make_float2(v0, v1);
                if (Ch) {
                    const __half2 h = __floats2half2_rn(v0, v1);
                    *reinterpret_cast<uint32_t*>(&Ch[tiled_idx(row, colb, M)]) = bits2(h);
                }
            }
        }
    }
}

// =====================================================================
// FA2 attention — single-plane Q (register P, occ 3).
// =====================================================================
#define A_OFFQ  1024
#define A_OFFKV (A_OFFQ + 8192)
#define A_SMEM  (A_OFFKV + 32768)     // 41984

__global__ void __launch_bounds__(128, 3)
attn_tc(const hf* __restrict__ QKVh,
        const hf* __restrict__ Kmh,
        hf* __restrict__ OH)
{
    extern __shared__ char smem[];
    const uint32_t sb = smem_u32(smem);
    const int bt  = blockIdx.x >> 4;
    const int h   = blockIdx.x & 15;
    const int tid = threadIdx.x;
    const int lane = tid & 31;
    const int wq   = tid >> 5;

    if (tid == 0) { MBARRIER_INIT(sb, 1); MBARRIER_INIT(sb + 8, 1); }

    #pragma unroll
    for (int seg = 0; seg < 2; seg++) {
        const hf* src = QKVh + ((size_t)(2 * h + seg) * LROWS + bt * 64) * 32;
        #pragma unroll
        for (int it = 0; it < 2; it++) {
            const int idx = tid + it * 128;
            const uint4 v = reinterpret_cast<const uint4*>(src)[idx];
            *reinterpret_cast<uint4*>(smem + A_OFFQ + seg * 4096 + idx * 16) = v;
        }
    }
    __syncthreads();

    auto issueKV = [&](int t) {
        const int st = t & 1;
        const uint32_t mb = sb + 8 * st;
        const uint32_t dst = sb + A_OFFKV + st * 16384;
        MBARRIER_EXPECT_TX(mb, 16384u);
        const hf* PH; size_t rbase, nr; int kcK, kcV;
        if (t < 16) { PH = Kmh;  rbase = (size_t)bt * 1024 + t * 64; nr = NMEDIA; kcK = 2*h;      kcV = 32 + 2*h; }
        else        { PH = QKVh; rbase = (size_t)bt * 64;            nr = LROWS;  kcK = 32 + 2*h; kcV = 64 + 2*h; }
        bulk_g2s(dst,          PH + ((size_t)kcK * nr + rbase) * 32,       4096, mb);
        bulk_g2s(dst +  4096,  PH + ((size_t)(kcK + 1) * nr + rbase) * 32, 4096, mb);
        bulk_g2s(dst +  8192,  PH + ((size_t)kcV * nr + rbase) * 32,       4096, mb);
        bulk_g2s(dst + 12288,  PH + ((size_t)(kcV + 1) * nr + rbase) * 32, 4096, mb);
    };
    if (tid == 0) issueKV(0);

    uint32_t qH[4][4];
    #pragma unroll
    for (int s = 0; s < 4; s++) {
        const int row = wq * 16 + (lane & 15);
        const int qq = (((s & 1) * 2 + (lane >> 4)) ^ ((row >> 1) & 3));
        ldmx4(qH[s], sb + A_OFFQ + (s >> 1) * 4096 + row * 64 + (qq << 4));
    }

    float mrow[2] = {-INFINITY, -INFINITY};
    float lrow[2] = {0.f, 0.f};
    float acc[4][2][4];
    #pragma unroll
    for (int d = 0; d < 4; d++)
        #pragma unroll
        for (int j = 0; j < 2; j++)
            #pragma unroll
            for (int q = 0; q < 4; q++) acc[d][j][q] = 0.f;

    for (int t = 0; t < 17; t++) {
        if (tid == 0 && t + 1 < 17) issueKV(t + 1);
        MBARRIER_WAIT_PARITY(sb + 8 * (t & 1), (t >> 1) & 1);
        const uint32_t kb = sb + A_OFFKV + (t & 1) * 16384;

        float sc[4][2][4];
        #pragma unroll
        for (int kg = 0; kg < 4; kg++)
            #pragma unroll
            for (int j = 0; j < 2; j++)
                #pragma unroll
                for (int q = 0; q < 4; q++) sc[kg][j][q] = 0.f;
        #pragma unroll
        for (int s = 0; s < 4; s++) {
            #pragma unroll
            for (int kg = 0; kg < 4; kg++) {
                const int row = kg * 16 + (lane & 7) + ((lane >> 4) << 3);
                const int qq = (((s & 1) * 2 + ((lane >> 3) & 1)) ^ ((row >> 1) & 3));
                uint32_t tB[4];
                ldmx4(tB, kb + (s >> 1) * 4096 + row * 64 + (qq << 4));
                uint32_t b0[2] = {tB[0], tB[1]}, b1[2] = {tB[2], tB[3]};
                mma16816(sc[kg][0], qH[s], b0);
                mma16816(sc[kg][1], qH[s], b1);
            }
        }
        #pragma unroll
        for (int kg = 0; kg < 4; kg++)
            #pragma unroll
            for (int j = 0; j < 2; j++)
                #pragma unroll
                for (int q = 0; q < 4; q++) sc[kg][j][q] *= 0.125f;

        #pragma unroll
        for (int p = 0; p < 2; p++) {
            float m = -INFINITY;
            #pragma unroll
            for (int kg = 0; kg < 4; kg++)
                #pragma unroll
                for (int j = 0; j < 2; j++) {
                    m = fmaxf(m, sc[kg][j][p * 2]);
                    m = fmaxf(m, sc[kg][j][p * 2 + 1]);
                }
            m = fmaxf(m, __shfl_xor_sync(0xffffffffu, m, 1));
            m = fmaxf(m, __shfl_xor_sync(0xffffffffu, m, 2));
            const float mnew = fmaxf(mrow[p], m);
            const float fac = __expf(mrow[p] - mnew);
            float sum = 0.f;
            #pragma unroll
            for (int kg = 0; kg < 4; kg++)
                #pragma unroll
                for (int j = 0; j < 2; j++) {
                    const float e0 = __expf(sc[kg][j][p * 2]     - mnew);
                    const float e1 = __expf(sc[kg][j][p * 2 + 1] - mnew);
                    sc[kg][j][p * 2] = e0; sc[kg][j][p * 2 + 1] = e1;
                    sum += e0 + e1;
                }
            sum += __shfl_xor_sync(0xffffffffu, sum, 1);
            sum += __shfl_xor_sync(0xffffffffu, sum, 2);
            lrow[p] = lrow[p] * fac + sum;
            mrow[p] = mnew;
            #pragma unroll
            for (int d = 0; d < 4; d++)
                #pragma unroll
                for (int j = 0; j < 2; j++) {
                    acc[d][j][p * 2]     *= fac;
                    acc[d][j][p * 2 + 1] *= fac;
                }
        }

        #pragma unroll
        for (int kg = 0; kg < 4; kg++) {
            uint32_t pa[4];
            pa[0] = bits2(__floats2half2_rn(sc[kg][0][0], sc[kg][0][1]));
            pa[1] = bits2(__floats2half2_rn(sc[kg][0][2], sc[kg][0][3]));
            pa[2] = bits2(__floats2half2_rn(sc[kg][1][0], sc[kg][1][1]));
            pa[3] = bits2(__floats2half2_rn(sc[kg][1][2], sc[kg][1][3]));
            #pragma unroll
            for (int dg = 0; dg < 4; dg++) {
                const int key  = kg * 16 + (lane & 15);
                const int dinb = dg * 16 + ((lane >> 4) << 3);
                const int kcv  = dinb >> 5, din = dinb & 31;
                const int qq   = ((din >> 3) ^ ((key >> 1) & 3));
                uint32_t tV[4];
                ldmx4t(tV, kb + 8192 + kcv * 4096 + key * 64 + (qq << 4));
                uint32_t v0[2] = {tV[0], tV[1]}, v1[2] = {tV[2], tV[3]};
                mma16816(acc[dg][0], pa, v0);
                mma16816(acc[dg][1], pa, v1);
            }
        }
        __syncthreads();
    }

    #pragma unroll
    for (int p = 0; p < 2; p++) {
        const float inv = 1.0f / lrow[p];
        const int row = bt * 64 + wq * 16 + (lane >> 2) + 8 * p;
        #pragma unroll
        for (int dg = 0; dg < 4; dg++)
            #pragma unroll
            for (int j = 0; j < 2; j++) {
                const int col = h * 64 + dg * 16 + j * 8 + (lane & 3) * 2;
                const __half2 hh = __floats2half2_rn(acc[dg][j][p * 2] * inv,
                                                     acc[dg][j][p * 2 + 1] * inv);
                *reinterpret_cast<uint32_t*>(&OH[tiled_idx(row, col, LROWS)]) = bits2(hh);
            }
    }
}

// ---------------- orchestration (dual-stream graph fork) ----------------
extern "C" void kernel_launch(void* const* d_in, const int* in_sizes, int n_in,
                              void* d_out, int out_size)
{
    (void)in_sizes; (void)n_in; (void)out_size;
    const float* x       = (const float*)d_in[0];
    const float* latents = (const float*)d_in[1];
    const float* nm_g    = (const float*)d_in[2];
    const float* nm_b    = (const float*)d_in[3];
    const float* nl_g    = (const float*)d_in[4];
    const float* nl_b    = (const float*)d_in[5];
    const float* wq      = (const float*)d_in[6];
    const float* wkv     = (const float*)d_in[7];
    const float* wo      = (const float*)d_in[8];
    const float* ff_g    = (const float*)d_in[9];
    const float* ff_b    = (const float*)d_in[10];
    const float* w1      = (const float*)d_in[11];
    const float* w2      = (const float*)d_in[12];
    const float* fin_g   = (const float*)d_in[13];
    const float* fin_b   = (const float*)d_in[14];
    float* out = (float*)d_out;

    hf *xh, *kvmh, *lnh, *qkvh, *ath, *h1h;
    float *lat, *bias, *part;
    cudaGetSymbolAddress((void**)&xh,   g_xh);
    cudaGetSymbolAddress((void**)&kvmh, g_kvmh);
    cudaGetSymbolAddress((void**)&lat,  g_lat);
    cudaGetSymbolAddress((void**)&lnh,  g_lnh);
    cudaGetSymbolAddress((void**)&qkvh, g_qkvh);
    cudaGetSymbolAddress((void**)&ath,  g_ath);
    cudaGetSymbolAddress((void**)&h1h,  g_h1h);
    cudaGetSymbolAddress((void**)&bias, g_bias); cudaGetSymbolAddress((void**)&part, g_part);

    hf *wqkvT, *wkvG, *woT, *w1T, *w2T;
    cudaGetSymbolAddress((void**)&wqkvT, g_wqkvT);
    cudaGetSymbolAddress((void**)&wkvG,  g_wkvG);
    cudaGetSymbolAddress((void**)&woT,   g_woT);
    cudaGetSymbolAddress((void**)&w1T,   g_w1T);
    cudaGetSymbolAddress((void**)&w2T,   g_w2T);

    cudaFuncSetAttribute(gemm1_tc, cudaFuncAttributeMaxDynamicSharedMemorySize, G1_SMEM);
    cudaFuncSetAttribute(attn_tc,  cudaFuncAttributeMaxDynamicSharedMemorySize, A_SMEM);
    const dim3 tb(32, 8);

    cudaStream_t s2;
    cudaStreamCreate(&s2);
    cudaEvent_t eFork, eKv[DEPTHL];
    cudaEventCreateWithFlags(&eFork, cudaEventDisableTiming);
    for (int i = 0; i < DEPTHL; i++) cudaEventCreateWithFlags(&eKv[i], cudaEventDisableTiming);

    // ---- kv-path prerequisites on main stream ----
    wsplit_kernel<<<dim3(NKV/32, DIMC/32, DEPTHL), tb>>>(wkv, nm_g, wkvG, DIMC, NKV, 0, NKV);
    bias_kernel<<<dim3(NKV/32, DEPTHL), 256>>>(nm_b, wkv, bias);
    ln_kernel<<<NMEDIA, 128>>>(x, nullptr, xh, nullptr, nullptr, NMEDIA);
    cudaEventRecord(eFork, 0);
    cudaStreamWaitEvent(s2, eFork, 0);

    // ---- kv_media per layer on stream 2 ----
    for (int i = 0; i < DEPTHL; i++) {
        gemm1_tc<<<dim3(NKV/128, NMEDIA/128), 256, G1_SMEM, s2>>>(
            xh, wkvG + (size_t)i*NKV*DIMC, nullptr, kvmh + (size_t)i*NMEDIA*NKV,
            NMEDIA, NKV, DIMC, bias + (size_t)i*NKV, 0,
            0, 0, 0, 1, nullptr);
        cudaEventRecord(eKv[i], s2);
    }

    // ---- latent-path prep on main stream ----
    wsplit_kernel<<<dim3(DIMC/32, DIMC/32, DEPTHL), tb>>>(wq,  nullptr, wqkvT, DIMC, DIMC, 0,    NQKV);
    wsplit_kernel<<<dim3(NKV/32,  DIMC/32, DEPTHL), tb>>>(wkv, nullptr, wqkvT, DIMC, NKV,  DIMC, NQKV);
    wsplit_kernel<<<dim3(DIMC/32, DIMC/32, DEPTHL), tb>>>(wo,  nullptr, woT,   DIMC, DIMC, 0,    DIMC);
    wsplit_kernel<<<dim3(FFD/32,  DIMC/32, DEPTHL), tb>>>(w1,  nullptr, w1T,   DIMC, FFD,  0,    FFD);
    wsplit_kernel<<<dim3(DIMC/32, FFD/32,  DEPTHL), tb>>>(w2,  nullptr, w2T,   FFD,  DIMC, 0,    DIMC);
    init_lat_kernel<<<(LROWS * DIMC) / 256, 256>>>(latents, lat);
    ln_kernel<<<LROWS, 128>>>(lat, nullptr, lnh, nl_g, nl_b, LROWS);

    for (int i = 0; i < DEPTHL; i++) {
        gemm1_tc<<<dim3(NQKV/128, LROWS/128), 256, G1_SMEM>>>(
            lnh, wqkvT + (size_t)i*NQKV*DIMC,
            nullptr, qkvh, LROWS, NQKV, DIMC, nullptr, 0,
            0, 0, 0, 1, nullptr);
        cudaStreamWaitEvent(0, eKv[i], 0);
        attn_tc<<<BTOT * HEADS, 128, A_SMEM>>>(
            qkvh, kvmh + (size_t)i*NMEDIA*NKV, ath);
        gemm1_tc<<<dim3(DIMC/128, LROWS/128, 2), 256, G1_SMEM>>>(
            ath, woT + (size_t)i*DIMC*DIMC,
            nullptr, nullptr, LROWS, DIMC, DIMC, nullptr, 0,
            0, 0, 0, 2, part);
        lnred_kernel<<<LROWS, 128>>>(part, 2, lat, lat, nullptr, lnh,
                                     ff_g + (size_t)i*DIMC, ff_b + (size_t)i*DIMC);
        gemm1_tc<<<dim3(FFD/128, LROWS/128), 256, G1_SMEM>>>(
            lnh, w1T + (size_t)i*FFD*DIMC,
            nullptr, h1h, LROWS, FFD, DIMC, nullptr, 1,
            0, 0, 0, 1, nullptr);
        gemm1_tc<<<dim3(DIMC/128, LROWS/128, 4), 256, G1_SMEM>>>(
            h1h, w2T + (size_t)i*DIMC*FFD,
            nullptr, nullptr, LROWS, DIMC, FFD, nullptr, 0,
            0, 0, 0, 4, part);
        if (i + 1 < DEPTHL) {
            lnred_kernel<<<LROWS, 128>>>(part, 4, lat, lat, nullptr, lnh,
                                         nl_g + (size_t)(i+1)*DIMC, nl_b + (size_t)(i+1)*DIMC);
        } else {
            lnred_kernel<<<LROWS, 128>>>(part, 4, lat, nullptr, out, nullptr,
                                         fin_g, fin_b);
        }
    }
}

// round 17
// speedup vs baseline: 1.0809x; 1.0696x over previous
#include <cuda_runtime.h>
#include <cuda_fp16.h>
#include <math.h>
#include <stdint.h>

// ---------------- problem constants ----------------
#define DIMC   1024
#define DEPTHL 6
#define HEADS  16
#define DHEAD  64
#define NKV    2048
#define NQKV   3072
#define FFD    4096
#define BTOT   32
#define MEDIA  1024
#define NMEDIA (BTOT*MEDIA)          // 32768
#define NLAT   64
#define LROWS  (BTOT*NLAT)           // 2048

typedef __half hf;

// ---------------- scratch ----------------
__device__ __align__(1024) hf    g_xh  [(size_t)NMEDIA*DIMC];
__device__ __align__(1024) hf    g_kvmh[(size_t)DEPTHL*NMEDIA*NKV];
__device__ float g_lat [LROWS*DIMC];
__device__ __align__(1024) hf    g_lnh [LROWS*DIMC];
__device__ __align__(1024) hf    g_qkvh[(size_t)LROWS*NQKV];
__device__ __align__(1024) hf    g_ath [LROWS*DIMC];
__device__ __align__(1024) hf    g_h1h [(size_t)LROWS*FFD];
__device__ float g_bias[DEPTHL*NKV];
__device__ float g_part[(size_t)4*LROWS*DIMC];

// weight planes (single fp16, B-side), chunk-tiled [K/32][N][32]
__device__ __align__(1024) hf g_wqkvT[(size_t)DEPTHL*NQKV*DIMC];
__device__ __align__(1024) hf g_wkvG [(size_t)DEPTHL*NKV*DIMC];
__device__ __align__(1024) hf g_woT  [(size_t)DEPTHL*DIMC*DIMC];
__device__ __align__(1024) hf g_w1T  [(size_t)DEPTHL*FFD*DIMC];
__device__ __align__(1024) hf g_w2T  [(size_t)DEPTHL*DIMC*FFD];

// ---------------- helpers ----------------
__device__ __forceinline__ uint32_t smem_u32(const void* p) {
    return (uint32_t)__cvta_generic_to_shared(p);
}
__device__ __forceinline__ size_t tiled_idx(int row, int k, int nrows) {
    const int kc = k >> 5, kin = k & 31;
    const int q = kin >> 3, b = kin & 7;
    const int qs = q ^ ((row >> 1) & 3);
    return ((size_t)kc * nrows + row) * 32 + qs * 8 + b;
}
__device__ __forceinline__ void bulk_g2s(uint32_t dst, const void* src, uint32_t bytes, uint32_t mbar) {
    asm volatile("cp.async.bulk.shared::cluster.global.mbarrier::complete_tx::bytes [%0], [%1], %2, [%3];"
                 :: "r"(dst), "l"(src), "r"(bytes), "r"(mbar) : "memory");
}
#define MBARRIER_INIT(addr, cnt) \
    asm volatile("mbarrier.init.shared.b64 [%0], %1;" :: "r"(addr), "r"(cnt) : "memory")
#define MBARRIER_EXPECT_TX(addr, tx) \
    asm volatile("mbarrier.arrive.expect_tx.shared.b64 _, [%0], %1;" :: "r"(addr), "r"(tx) : "memory")
#define MBARRIER_ARRIVE(addr) \
    asm volatile("mbarrier.arrive.shared.b64 _, [%0];" :: "r"(addr) : "memory")
#define MBARRIER_WAIT_PARITY(addr, par) do { \
    uint32_t _m = (addr), _p = (par), _d; \
    asm volatile("{\n\t.reg .pred p;\n\t" \
        "mbarrier.try_wait.parity.acquire.cta.shared::cta.b64 p, [%1], %2;\n\t" \
        "selp.b32 %0, 1, 0, p;\n\t}" : "=r"(_d) : "r"(_m), "r"(_p) : "memory"); \
    if (!_d) { \
        asm volatile("{\n\t.reg .pred P1;\n\t" \
            "WL_%=:\n\t" \
            "mbarrier.try_wait.parity.acquire.cta.shared::cta.b64 P1, [%0], %1, 0x989680;\n\t" \
            "@P1 bra.uni WD_%=;\n\tbra.uni WL_%=;\n\tWD_%=:\n\t}" \
            :: "r"(_m), "r"(_p) : "memory"); \
    } } while (0)

__device__ __forceinline__ void ldmx4(uint32_t* r, uint32_t a) {
    asm volatile("ldmatrix.sync.aligned.m8n8.x4.shared.b16 {%0,%1,%2,%3}, [%4];"
                 : "=r"(r[0]), "=r"(r[1]), "=r"(r[2]), "=r"(r[3]) : "r"(a));
}
__device__ __forceinline__ void ldmx4t(uint32_t* r, uint32_t a) {
    asm volatile("ldmatrix.sync.aligned.m8n8.x4.trans.shared.b16 {%0,%1,%2,%3}, [%4];"
                 : "=r"(r[0]), "=r"(r[1]), "=r"(r[2]), "=r"(r[3]) : "r"(a));
}
__device__ __forceinline__ void mma16816(float* d, const uint32_t* a, const uint32_t* b) {
    asm volatile("mma.sync.aligned.m16n8k16.row.col.f32.f16.f16.f32 "
                 "{%0,%1,%2,%3},{%4,%5,%6,%7},{%8,%9},{%0,%1,%2,%3};"
                 : "+f"(d[0]), "+f"(d[1]), "+f"(d[2]), "+f"(d[3])
                 : "r"(a[0]), "r"(a[1]), "r"(a[2]), "r"(a[3]),
                   "r"(b[0]), "r"(b[1]));
}
__device__ __forceinline__ uint32_t bits2(__half2 h) {
    return *reinterpret_cast<uint32_t*>(&h);
}

// ---------------- LayerNorm: fp32 in -> fp32 out and/or tiled fp16 hi plane ----
__global__ void ln_kernel(const float* __restrict__ in,
                          float* __restrict__ outF,
                          hf* __restrict__ outH,
                          const float* __restrict__ g, const float* __restrict__ b,
                          int nrows)
{
    const int row = blockIdx.x;
    const float* x = in + (size_t)row * DIMC;
    float s = 0.f, sq = 0.f;
    for (int c = threadIdx.x; c < DIMC; c += blockDim.x) {
        float v = x[c]; s += v; sq += v * v;
    }
    __shared__ float sh[64];
    #pragma unroll
    for (int o = 16; o > 0; o >>= 1) {
        s  += __shfl_down_sync(0xffffffffu, s,  o);
        sq += __shfl_down_sync(0xffffffffu, sq, o);
    }
    const int wid = threadIdx.x >> 5, lid = threadIdx.x & 31;
    if (lid == 0) { sh[wid] = s; sh[wid + 32] = sq; }
    __syncthreads();
    if (threadIdx.x == 0) {
        float ts = 0.f, tsq = 0.f;
        const int nw = blockDim.x >> 5;
        for (int i = 0; i < nw; i++) { ts += sh[i]; tsq += sh[i + 32]; }
        const float mean = ts * (1.0f / DIMC);
        const float var  = tsq * (1.0f / DIMC) - mean * mean;
        sh[0] = mean; sh[1] = rsqrtf(var + 1e-5f);
    }
    __syncthreads();
    const float mean = sh[0], rstd = sh[1];

    for (int k0 = threadIdx.x * 8; k0 < DIMC; k0 += blockDim.x * 8) {
        float v[8];
        #pragma unroll
        for (int e = 0; e < 8; e++) {
            float t = (x[k0 + e] - mean) * rstd;
            if (g) t = t * g[k0 + e] + b[k0 + e];
            v[e] = t;
        }
        if (outF) {
            float* o = outF + (size_t)row * DIMC + k0;
            #pragma unroll
            for (int e = 0; e < 8; e++) o[e] = v[e];
        }
        if (outH) {
            uint32_t hq[4];
            #pragma unroll
            for (int e = 0; e < 4; e++)
                hq[e] = bits2(__floats2half2_rn(v[2*e], v[2*e+1]));
            *reinterpret_cast<uint4*>(&outH[tiled_idx(row, k0, nrows)]) =
                make_uint4(hq[0], hq[1], hq[2], hq[3]);
        }
    }
}

// ---------------- fused split-K reduce + residual + LayerNorm ----------------
__global__ void __launch_bounds__(128)
lnred_kernel(const float* __restrict__ part, int S,
             const float* __restrict__ latin,
             float* __restrict__ latout,
             float* __restrict__ outF,
             hf* __restrict__ outH,
             const float* __restrict__ g, const float* __restrict__ b)
{
    const int row = blockIdx.x;
    const int tid = threadIdx.x;
    const size_t base = (size_t)row * DIMC + tid * 8;
    float v[8];
    #pragma unroll
    for (int e = 0; e < 8; e++) v[e] = latin[base + e];
    for (int s = 0; s < S; s++) {
        const float* p = part + (size_t)s * LROWS * DIMC + base;
        #pragma unroll
        for (int e = 0; e < 8; e++) v[e] += p[e];
    }
    if (latout) {
        #pragma unroll
        for (int e = 0; e < 8; e++) latout[base + e] = v[e];
    }
    float s1 = 0.f, s2 = 0.f;
    #pragma unroll
    for (int e = 0; e < 8; e++) { s1 += v[e]; s2 += v[e] * v[e]; }
    __shared__ float sh[8];
    #pragma unroll
    for (int o = 16; o > 0; o >>= 1) {
        s1 += __shfl_down_sync(0xffffffffu, s1, o);
        s2 += __shfl_down_sync(0xffffffffu, s2, o);
    }
    const int wid = tid >> 5, lid = tid & 31;
    if (lid == 0) { sh[wid] = s1; sh[wid + 4] = s2; }
    __syncthreads();
    if (tid == 0) {
        float ts = sh[0] + sh[1] + sh[2] + sh[3];
        float tq = sh[4] + sh[5] + sh[6] + sh[7];
        const float mean = ts * (1.0f / DIMC);
        const float var  = tq * (1.0f / DIMC) - mean * mean;
        sh[0] = mean; sh[1] = rsqrtf(var + 1e-5f);
    }
    __syncthreads();
    const float mean = sh[0], rstd = sh[1];
    const int k0 = tid * 8;
    float t[8];
    #pragma unroll
    for (int e = 0; e < 8; e++)
        t[e] = (v[e] - mean) * rstd * g[k0 + e] + b[k0 + e];
    if (outF) {
        float* o = outF + base;
        #pragma unroll
        for (int e = 0; e < 8; e++) o[e] = t[e];
    }
    if (outH) {
        uint32_t hq[4];
        #pragma unroll
        for (int e = 0; e < 4; e++)
            hq[e] = bits2(__floats2half2_rn(t[2*e], t[2*e+1]));
        *reinterpret_cast<uint4*>(&outH[tiled_idx(row, k0, LROWS)]) =
            make_uint4(hq[0], hq[1], hq[2], hq[3]);
    }
}

// ---------------- bias: all layers, k-parallel ----------------
__global__ void bias_kernel(const float* __restrict__ nm_b,
                            const float* __restrict__ wkv, float* __restrict__ out)
{
    const int layer = blockIdx.y;
    const int tid = threadIdx.x;
    const int n  = blockIdx.x * 32 + (tid & 31);
    const int ks = tid >> 5;
    const float* bv = nm_b + (size_t)layer * DIMC;
    const float* W  = wkv  + (size_t)layer * DIMC * NKV;
    float s = 0.f;
    #pragma unroll 4
    for (int k = ks * 128; k < ks * 128 + 128; k++)
        s += bv[k] * __ldg(&W[(size_t)k * NKV + n]);
    __shared__ float red[8][32];
    red[ks][tid & 31] = s;
    __syncthreads();
    if (ks == 0) {
        float t = 0.f;
        #pragma unroll
        for (int i = 0; i < 8; i++) t += red[i][tid & 31];
        out[(size_t)layer * NKV + n] = t;
    }
}

__global__ void init_lat_kernel(const float* __restrict__ latents, float* __restrict__ lat)
{
    const int idx = blockIdx.x * blockDim.x + threadIdx.x;
    lat[idx] = latents[idx & (NLAT * DIMC - 1)];
}

// ---------------- weight transpose + gamma + fp16 quantize (batched over depth) ----
__global__ void wsplit_kernel(const float* __restrict__ W0, const float* __restrict__ g0,
                              hf* __restrict__ T0, int K, int N, int nofs, int ntot)
{
    const int z = blockIdx.z;
    const float* W = W0 + (size_t)z * K * N;
    const float* g = g0 ? g0 + (size_t)z * K : nullptr;
    hf* T = T0 + (size_t)z * ntot * K;
    __shared__ float t[32][33];
    const int n0 = blockIdx.x * 32, k0 = blockIdx.y * 32;
    const int tx = threadIdx.x, ty = threadIdx.y;
    #pragma unroll
    for (int i = 0; i < 4; i++) {
        float v = W[(size_t)(k0 + ty + 8 * i) * N + n0 + tx];
        if (g) v *= g[k0 + ty + 8 * i];
        t[ty + 8 * i][tx] = v;
    }
    __syncthreads();
    #pragma unroll
    for (int i = 0; i < 4; i++) {
        const int n = n0 + ty + 8 * i, k = k0 + tx;
        T[tiled_idx(nofs + n, k, ntot)] = __float2half_rn(t[tx][ty + 8 * i]);
    }
}

// =====================================================================
// 1-term fp16 HMMA GEMM, occ 2, 2 x K64 stages, empty-barrier pipeline.
// Consumers never lockstep: each warp arrives on empty[slot]; only the
// producer (tid 0) waits empty before re-filling that slot.
// mbarriers: full[2] @ sb+0,+8 (count 1); empty[2] @ sb+16,+24 (count 8).
// grid.z = layers (lstr*) OR split-K partitions (splitk>1, Cpart).
// =====================================================================
#define NSTG1 2
#define STG1  32768                   // [A c0 8K | A c1 8K | B c0 8K | B c1 8K]
#define G1_SMEM (1024 + NSTG1*STG1)   // 66560

__global__ void __launch_bounds__(256, 2)
gemm1_tc(const hf* __restrict__ Ah, const hf* __restrict__ B0,
         float* __restrict__ Cf, hf* __restrict__ Ch0,
         int M, int N, int K,
         const float* __restrict__ bias0, int dogelu,
         size_t lstrB, size_t lstrC, int lstrBias,
         int splitk, float* __restrict__ Cpart)
{
    extern __shared__ char smem[];
    const uint32_t sb = smem_u32(smem);
    const int tid  = threadIdx.x;
    const int lane = tid & 31;
    const int wid  = tid >> 5;
    const int wm   = wid & 1;
    const int wn   = wid >> 1;
    const int bm   = blockIdx.y * 128;
    const int bn   = blockIdx.x * 128;
    const int z    = blockIdx.z;

    const hf* B = B0;
    hf* Ch = Ch0;
    const float* bias = bias0;
    const int nc = K >> 5;
    int ncl = nc, c0 = 0;
    if (splitk > 1) { ncl = nc / splitk; c0 = z * ncl; }
    else if (z) {
        B += (size_t)z * lstrB;
        if (Ch0) Ch += (size_t)z * lstrC;
        if (bias0) bias += (size_t)z * lstrBias;
    }
    const int nst = ncl >> 1;          // K64 stages; nst in {4,8,16}

    if (tid == 0) {
        MBARRIER_INIT(sb,      1); MBARRIER_INIT(sb + 8,  1);   // full
        MBARRIER_INIT(sb + 16, 8); MBARRIER_INIT(sb + 24, 8);   // empty (8 warps)
    }
    __syncthreads();

    float acc[4][4][4];
    #pragma unroll
    for (int i = 0; i < 4; i++)
        #pragma unroll
        for (int j = 0; j < 4; j++)
            #pragma unroll
            for (int q = 0; q < 4; q++) acc[i][j][q] = 0.f;

    auto issue = [&](int si) {
        const uint32_t mb  = sb + 8 * (si & 1);
        const uint32_t dst = sb + 1024 + (si & 1) * STG1;
        MBARRIER_EXPECT_TX(mb, 32768u);
        #pragma unroll
        for (int half = 0; half < 2; half++) {
            const int gc = c0 + 2 * si + half;
            bulk_g2s(dst + half * 8192,         Ah + ((size_t)gc * M + bm) * 32, 8192, mb);
            bulk_g2s(dst + 16384 + half * 8192, B  + ((size_t)gc * N + bn) * 32, 8192, mb);
        }
    };
    if (tid == 0) { issue(0); issue(1); }   // nst >= 4 always

    for (int si = 0; si < nst; si++) {
        MBARRIER_WAIT_PARITY(sb + 8 * (si & 1), (si >> 1) & 1);
        const uint32_t base = sb + 1024 + (si & 1) * STG1;
        #pragma unroll
        for (int u = 0; u < 4; u++) {
            const int half = u >> 1, s16 = u & 1;
            const uint32_t stA = base + half * 8192;
            const uint32_t stB = base + 16384 + half * 8192;
            uint32_t aH[16], bf[8];
            #pragma unroll
            for (int mi = 0; mi < 4; mi++) {
                const int row = wm * 64 + mi * 16 + (lane & 15);
                const int q   = s16 * 2 + (lane >> 4);
                ldmx4(aH + 4 * mi, stA + row * 64 + ((q ^ ((row >> 1) & 3)) << 4));
            }
            #pragma unroll
            for (int ni = 0; ni < 2; ni++) {
                const int row = wn * 32 + ni * 16 + (lane & 7) + ((lane >> 4) << 3);
                const int q   = s16 * 2 + ((lane >> 3) & 1);
                uint32_t t[4];
                ldmx4(t, stB + row * 64 + ((q ^ ((row >> 1) & 3)) << 4));
                bf[ni*4+0] = t[0]; bf[ni*4+1] = t[1]; bf[ni*4+2] = t[2]; bf[ni*4+3] = t[3];
            }
            #pragma unroll
            for (int mi = 0; mi < 4; mi++)
                #pragma unroll
                for (int j = 0; j < 4; j++)
                    mma16816(acc[mi][j], aH + 4 * mi, bf + 2 * j);
        }
        // this warp is done reading slot (si&1): release it
        if (lane == 0) MBARRIER_ARRIVE(sb + 16 + 8 * (si & 1));
        // producer refills the slot once all 8 warps have released it
        if (tid == 0 && si + NSTG1 < nst) {
            MBARRIER_WAIT_PARITY(sb + 16 + 8 * (si & 1), (si >> 1) & 1);
            issue(si + NSTG1);
        }
    }

    if (Cpart) {
        float* P = Cpart + (size_t)z * M * N;
        #pragma unroll
        for (int mi = 0; mi < 4; mi++)
            #pragma unroll
            for (int j = 0; j < 4; j++) {
                const int colb = bn + wn * 32 + j * 8 + (lane & 3) * 2;
                #pragma unroll
                for (int p = 0; p < 2; p++) {
                    const int row = bm + wm * 64 + mi * 16 + (lane >> 2) + 8 * p;
                    *reinterpret_cast<float2*>(&P[(size_t)row * N + colb]) =
                        make_float2(acc[mi][j][p * 2], acc[mi][j][p * 2 + 1]);
                }
            }
        return;
    }
    #pragma unroll
    for (int mi = 0; mi < 4; mi++) {
        #pragma unroll
        for (int j = 0; j < 4; j++) {
            const int colb = bn + wn * 32 + j * 8 + (lane & 3) * 2;
            #pragma unroll
            for (int p = 0; p < 2; p++) {
                const int row = bm + wm * 64 + mi * 16 + (lane >> 2) + 8 * p;
                float v0 = acc[mi][j][p * 2], v1 = acc[mi][j][p * 2 + 1];
                if (bias) { v0 += bias[colb]; v1 += bias[colb + 1]; }
                if (dogelu) {
                    v0 = 0.5f * v0 * (1.f + erff(v0 * 0.70710678118654752f));
                    v1 = 0.5f * v1 * (1.f + erff(v1 * 0.70710678118654752f));
                }
                if (Cf) *reinterpret_cast<float2*>(&Cf[(size_t)row * N + colb]) = make_float2(v0, v1);
                if (Ch) {
                    const __half2 h = __floats2half2_rn(v0, v1);
                    *reinterpret_cast<uint32_t*>(&Ch[tiled_idx(row, colb, M)]) = bits2(h);
                }
            }
        }
    }
}

// =====================================================================
// FA2 attention — single-plane Q (register P, occ 3).
// =====================================================================
#define A_OFFQ  1024
#define A_OFFKV (A_OFFQ + 8192)
#define A_SMEM  (A_OFFKV + 32768)     // 41984

__global__ void __launch_bounds__(128, 3)
attn_tc(const hf* __restrict__ QKVh,
        const hf* __restrict__ Kmh,
        hf* __restrict__ OH)
{
    extern __shared__ char smem[];
    const uint32_t sb = smem_u32(smem);
    const int bt  = blockIdx.x >> 4;
    const int h   = blockIdx.x & 15;
    const int tid = threadIdx.x;
    const int lane = tid & 31;
    const int wq   = tid >> 5;

    if (tid == 0) { MBARRIER_INIT(sb, 1); MBARRIER_INIT(sb + 8, 1); }

    #pragma unroll
    for (int seg = 0; seg < 2; seg++) {
        const hf* src = QKVh + ((size_t)(2 * h + seg) * LROWS + bt * 64) * 32;
        #pragma unroll
        for (int it = 0; it < 2; it++) {
            const int idx = tid + it * 128;
            const uint4 v = reinterpret_cast<const uint4*>(src)[idx];
            *reinterpret_cast<uint4*>(smem + A_OFFQ + seg * 4096 + idx * 16) = v;
        }
    }
    __syncthreads();

    auto issueKV = [&](int t) {
        const int st = t & 1;
        const uint32_t mb = sb + 8 * st;
        const uint32_t dst = sb + A_OFFKV + st * 16384;
        MBARRIER_EXPECT_TX(mb, 16384u);
        const hf* PH; size_t rbase, nr; int kcK, kcV;
        if (t < 16) { PH = Kmh;  rbase = (size_t)bt * 1024 + t * 64; nr = NMEDIA; kcK = 2*h;      kcV = 32 + 2*h; }
        else        { PH = QKVh; rbase = (size_t)bt * 64;            nr = LROWS;  kcK = 32 + 2*h; kcV = 64 + 2*h; }
        bulk_g2s(dst,          PH + ((size_t)kcK * nr + rbase) * 32,       4096, mb);
        bulk_g2s(dst +  4096,  PH + ((size_t)(kcK + 1) * nr + rbase) * 32, 4096, mb);
        bulk_g2s(dst +  8192,  PH + ((size_t)kcV * nr + rbase) * 32,       4096, mb);
        bulk_g2s(dst + 12288,  PH + ((size_t)(kcV + 1) * nr + rbase) * 32, 4096, mb);
    };
    if (tid == 0) issueKV(0);

    uint32_t qH[4][4];
    #pragma unroll
    for (int s = 0; s < 4; s++) {
        const int row = wq * 16 + (lane & 15);
        const int qq = (((s & 1) * 2 + (lane >> 4)) ^ ((row >> 1) & 3));
        ldmx4(qH[s], sb + A_OFFQ + (s >> 1) * 4096 + row * 64 + (qq << 4));
    }

    float mrow[2] = {-INFINITY, -INFINITY};
    float lrow[2] = {0.f, 0.f};
    float acc[4][2][4];
    #pragma unroll
    for (int d = 0; d < 4; d++)
        #pragma unroll
        for (int j = 0; j < 2; j++)
            #pragma unroll
            for (int q = 0; q < 4; q++) acc[d][j][q] = 0.f;

    for (int t = 0; t < 17; t++) {
        if (tid == 0 && t + 1 < 17) issueKV(t + 1);
        MBARRIER_WAIT_PARITY(sb + 8 * (t & 1), (t >> 1) & 1);
        const uint32_t kb = sb + A_OFFKV + (t & 1) * 16384;

        float sc[4][2][4];
        #pragma unroll
        for (int kg = 0; kg < 4; kg++)
            #pragma unroll
            for (int j = 0; j < 2; j++)
                #pragma unroll
                for (int q = 0; q < 4; q++) sc[kg][j][q] = 0.f;
        #pragma unroll
        for (int s = 0; s < 4; s++) {
            #pragma unroll
            for (int kg = 0; kg < 4; kg++) {
                const int row = kg * 16 + (lane & 7) + ((lane >> 4) << 3);
                const int qq = (((s & 1) * 2 + ((lane >> 3) & 1)) ^ ((row >> 1) & 3));
                uint32_t tB[4];
                ldmx4(tB, kb + (s >> 1) * 4096 + row * 64 + (qq << 4));
                uint32_t b0[2] = {tB[0], tB[1]}, b1[2] = {tB[2], tB[3]};
                mma16816(sc[kg][0], qH[s], b0);
                mma16816(sc[kg][1], qH[s], b1);
            }
        }
        #pragma unroll
        for (int kg = 0; kg < 4; kg++)
            #pragma unroll
            for (int j = 0; j < 2; j++)
                #pragma unroll
                for (int q = 0; q < 4; q++) sc[kg][j][q] *= 0.125f;

        #pragma unroll
        for (int p = 0; p < 2; p++) {
            float m = -INFINITY;
            #pragma unroll
            for (int kg = 0; kg < 4; kg++)
                #pragma unroll
                for (int j = 0; j < 2; j++) {
                    m = fmaxf(m, sc[kg][j][p * 2]);
                    m = fmaxf(m, sc[kg][j][p * 2 + 1]);
                }
            m = fmaxf(m, __shfl_xor_sync(0xffffffffu, m, 1));
            m = fmaxf(m, __shfl_xor_sync(0xffffffffu, m, 2));
            const float mnew = fmaxf(mrow[p], m);
            const float fac = __expf(mrow[p] - mnew);
            float sum = 0.f;
            #pragma unroll
            for (int kg = 0; kg < 4; kg++)
                #pragma unroll
                for (int j = 0; j < 2; j++) {
                    const float e0 = __expf(sc[kg][j][p * 2]     - mnew);
                    const float e1 = __expf(sc[kg][j][p * 2 + 1] - mnew);
                    sc[kg][j][p * 2] = e0; sc[kg][j][p * 2 + 1] = e1;
                    sum += e0 + e1;
                }
            sum += __shfl_xor_sync(0xffffffffu, sum, 1);
            sum += __shfl_xor_sync(0xffffffffu, sum, 2);
            lrow[p] = lrow[p] * fac + sum;
            mrow[p] = mnew;
            #pragma unroll
            for (int d = 0; d < 4; d++)
                #pragma unroll
                for (int j = 0; j < 2; j++) {
                    acc[d][j][p * 2]     *= fac;
                    acc[d][j][p * 2 + 1] *= fac;
                }
        }

        #pragma unroll
        for (int kg = 0; kg < 4; kg++) {
            uint32_t pa[4];
            pa[0] = bits2(__floats2half2_rn(sc[kg][0][0], sc[kg][0][1]));
            pa[1] = bits2(__floats2half2_rn(sc[kg][0][2], sc[kg][0][3]));
            pa[2] = bits2(__floats2half2_rn(sc[kg][1][0], sc[kg][1][1]));
            pa[3] = bits2(__floats2half2_rn(sc[kg][1][2], sc[kg][1][3]));
            #pragma unroll
            for (int dg = 0; dg < 4; dg++) {
                const int key  = kg * 16 + (lane & 15);
                const int dinb = dg * 16 + ((lane >> 4) << 3);
                const int kcv  = dinb >> 5, din = dinb & 31;
                const int qq   = ((din >> 3) ^ ((key >> 1) & 3));
                uint32_t tV[4];
                ldmx4t(tV, kb + 8192 + kcv * 4096 + key * 64 + (qq << 4));
                uint32_t v0[2] = {tV[0], tV[1]}, v1[2] = {tV[2], tV[3]};
                mma16816(acc[dg][0], pa, v0);
                mma16816(acc[dg][1], pa, v1);
            }
        }
        __syncthreads();
    }

    #pragma unroll
    for (int p = 0; p < 2; p++) {
        const float inv = 1.0f / lrow[p];
        const int row = bt * 64 + wq * 16 + (lane >> 2) + 8 * p;
        #pragma unroll
        for (int dg = 0; dg < 4; dg++)
            #pragma unroll
            for (int j = 0; j < 2; j++) {
                const int col = h * 64 + dg * 16 + j * 8 + (lane & 3) * 2;
                const __half2 hh = __floats2half2_rn(acc[dg][j][p * 2] * inv,
                                                     acc[dg][j][p * 2 + 1] * inv);
                *reinterpret_cast<uint32_t*>(&OH[tiled_idx(row, col, LROWS)]) = bits2(hh);
            }
    }
}

// ---------------- orchestration (dual-stream graph fork) ----------------
extern "C" void kernel_launch(void* const* d_in, const int* in_sizes, int n_in,
                              void* d_out, int out_size)
{
    (void)in_sizes; (void)n_in; (void)out_size;
    const float* x       = (const float*)d_in[0];
    const float* latents = (const float*)d_in[1];
    const float* nm_g    = (const float*)d_in[2];
    const float* nm_b    = (const float*)d_in[3];
    const float* nl_g    = (const float*)d_in[4];
    const float* nl_b    = (const float*)d_in[5];
    const float* wq      = (const float*)d_in[6];
    const float* wkv     = (const float*)d_in[7];
    const float* wo      = (const float*)d_in[8];
    const float* ff_g    = (const float*)d_in[9];
    const float* ff_b    = (const float*)d_in[10];
    const float* w1      = (const float*)d_in[11];
    const float* w2      = (const float*)d_in[12];
    const float* fin_g   = (const float*)d_in[13];
    const float* fin_b   = (const float*)d_in[14];
    float* out = (float*)d_out;

    hf *xh, *kvmh, *lnh, *qkvh, *ath, *h1h;
    float *lat, *bias, *part;
    cudaGetSymbolAddress((void**)&xh,   g_xh);
    cudaGetSymbolAddress((void**)&kvmh, g_kvmh);
    cudaGetSymbolAddress((void**)&lat,  g_lat);
    cudaGetSymbolAddress((void**)&lnh,  g_lnh);
    cudaGetSymbolAddress((void**)&qkvh, g_qkvh);
    cudaGetSymbolAddress((void**)&ath,  g_ath);
    cudaGetSymbolAddress((void**)&h1h,  g_h1h);
    cudaGetSymbolAddress((void**)&bias, g_bias); cudaGetSymbolAddress((void**)&part, g_part);

    hf *wqkvT, *wkvG, *woT, *w1T, *w2T;
    cudaGetSymbolAddress((void**)&wqkvT, g_wqkvT);
    cudaGetSymbolAddress((void**)&wkvG,  g_wkvG);
    cudaGetSymbolAddress((void**)&woT,   g_woT);
    cudaGetSymbolAddress((void**)&w1T,   g_w1T);
    cudaGetSymbolAddress((void**)&w2T,   g_w2T);

    cudaFuncSetAttribute(gemm1_tc, cudaFuncAttributeMaxDynamicSharedMemorySize, G1_SMEM);
    cudaFuncSetAttribute(attn_tc,  cudaFuncAttributeMaxDynamicSharedMemorySize, A_SMEM);
    const dim3 tb(32, 8);

    cudaStream_t s2;
    cudaStreamCreate(&s2);
    cudaEvent_t eFork, eKv[DEPTHL];
    cudaEventCreateWithFlags(&eFork, cudaEventDisableTiming);
    for (int i = 0; i < DEPTHL; i++) cudaEventCreateWithFlags(&eKv[i], cudaEventDisableTiming);

    // ---- kv-path prerequisites on main stream ----
    wsplit_kernel<<<dim3(NKV/32, DIMC/32, DEPTHL), tb>>>(wkv, nm_g, wkvG, DIMC, NKV, 0, NKV);
    bias_kernel<<<dim3(NKV/32, DEPTHL), 256>>>(nm_b, wkv, bias);
    ln_kernel<<<NMEDIA, 128>>>(x, nullptr, xh, nullptr, nullptr, NMEDIA);
    cudaEventRecord(eFork, 0);
    cudaStreamWaitEvent(s2, eFork, 0);

    // ---- kv_media per layer on stream 2 ----
    for (int i = 0; i < DEPTHL; i++) {
        gemm1_tc<<<dim3(NKV/128, NMEDIA/128), 256, G1_SMEM, s2>>>(
            xh, wkvG + (size_t)i*NKV*DIMC, nullptr, kvmh + (size_t)i*NMEDIA*NKV,
            NMEDIA, NKV, DIMC, bias + (size_t)i*NKV, 0,
            0, 0, 0, 1, nullptr);
        cudaEventRecord(eKv[i], s2);
    }

    // ---- latent-path prep on main stream ----
    wsplit_kernel<<<dim3(DIMC/32, DIMC/32, DEPTHL), tb>>>(wq,  nullptr, wqkvT, DIMC, DIMC, 0,    NQKV);
    wsplit_kernel<<<dim3(NKV/32,  DIMC/32, DEPTHL), tb>>>(wkv, nullptr, wqkvT, DIMC, NKV,  DIMC, NQKV);
    wsplit_kernel<<<dim3(DIMC/32, DIMC/32, DEPTHL), tb>>>(wo,  nullptr, woT,   DIMC, DIMC, 0,    DIMC);
    wsplit_kernel<<<dim3(FFD/32,  DIMC/32, DEPTHL), tb>>>(w1,  nullptr, w1T,   DIMC, FFD,  0,    FFD);
    wsplit_kernel<<<dim3(DIMC/32, FFD/32,  DEPTHL), tb>>>(w2,  nullptr, w2T,   FFD,  DIMC, 0,    DIMC);
    init_lat_kernel<<<(LROWS * DIMC) / 256, 256>>>(latents, lat);
    ln_kernel<<<LROWS, 128>>>(lat, nullptr, lnh, nl_g, nl_b, LROWS);

    for (int i = 0; i < DEPTHL; i++) {
        gemm1_tc<<<dim3(NQKV/128, LROWS/128), 256, G1_SMEM>>>(
            lnh, wqkvT + (size_t)i*NQKV*DIMC,
            nullptr, qkvh, LROWS, NQKV, DIMC, nullptr, 0,
            0, 0, 0, 1, nullptr);
        cudaStreamWaitEvent(0, eKv[i], 0);
        attn_tc<<<BTOT * HEADS, 128, A_SMEM>>>(
            qkvh, kvmh + (size_t)i*NMEDIA*NKV, ath);
        gemm1_tc<<<dim3(DIMC/128, LROWS/128, 2), 256, G1_SMEM>>>(
            ath, woT + (size_t)i*DIMC*DIMC,
            nullptr, nullptr, LROWS, DIMC, DIMC, nullptr, 0,
            0, 0, 0, 2, part);
        lnred_kernel<<<LROWS, 128>>>(part, 2, lat, lat, nullptr, lnh,
                                     ff_g + (size_t)i*DIMC, ff_b + (size_t)i*DIMC);
        gemm1_tc<<<dim3(FFD/128, LROWS/128), 256, G1_SMEM>>>(
            lnh, w1T + (size_t)i*FFD*DIMC,
            nullptr, h1h, LROWS, FFD, DIMC, nullptr, 1,
            0, 0, 0, 1, nullptr);
        gemm1_tc<<<dim3(DIMC/128, LROWS/128, 4), 256, G1_SMEM>>>(
            h1h, w2T + (size_t)i*DIMC*FFD,
            nullptr, nullptr, LROWS, DIMC, FFD, nullptr, 0,
            0, 0, 0, 4, part);
        if (i + 1 < DEPTHL) {
            lnred_kernel<<<LROWS, 128>>>(part, 4, lat, lat, nullptr, lnh,
                                         nl_g + (size_t)(i+1)*DIMC, nl_b + (size_t)(i+1)*DIMC);
        } else {
            lnred_kernel<<<LROWS, 128>>>(part, 4, lat, nullptr, out, nullptr,
                                         fin_g, fin_b);
        }
    }
}